// round 13
// baseline (speedup 1.0000x reference)
#include <cuda_runtime.h>
#include <cuda_fp16.h>
#include <math.h>
#include <cstdint>

#define BB 8
#define CI 64
#define CO 128
#define HH 256
#define WW 256

#define SUB (BB*CO*128*128)
#define MSK (BB*128*128)
#define OFF_LL  0
#define OFF_MLL (SUB)
#define OFF_LH  (SUB + MSK)
#define OFF_HL  (2*SUB + MSK)
#define OFF_HH  (3*SUB + MSK)
#define OFF_MLH (4*SUB + MSK)
#define OFF_MHL (4*SUB + 2*MSK)
#define OFF_MHH (4*SUB + 3*MSK)

#define PH 258

// Scratch
__device__ float g_x[(size_t)BB*CO*HH*WW];    // final GDN output (DWT input)
__device__ float g_ratio[BB*HH*WW];
__device__ float g_inv_sigma;
// zero-initialized; xprep writes interior only, so borders stay zero forever
__device__ uint4 g_xh4[(size_t)BB*PH*PH*8];   // padded NHWC fp16 of x*mask
__device__ __half g_wh[9*128*64];             // [tap][oc][ch] fp16 (spectral-normalized)
__device__ __half g_gh[128*128];              // gamma [oc][ch] fp16

__constant__ float c_h0[9] = {
    0.026748757410810f, -0.016864118442875f, -0.078223266528990f,
    0.266864118442875f,  0.602949018236360f,  0.266864118442875f,
   -0.078223266528990f, -0.016864118442875f,  0.026748757410810f};
__constant__ float c_h1[7] = {
    0.091271763114250f, -0.057543526228500f, -0.591271763114250f,
    1.115087052457000f, -0.591271763114250f, -0.057543526228500f,
    0.091271763114250f};

__device__ __forceinline__ int refl(int i, int n) {
    return i < 0 ? -i : (i >= n ? 2*n - 2 - i : i);
}
__device__ __forceinline__ uint32_t smem_u32(const void* p) {
    uint32_t a;
    asm("{ .reg .u64 t; cvta.to.shared.u64 t, %1; cvt.u32.u64 %0, t; }" : "=r"(a) : "l"(p));
    return a;
}
__device__ __forceinline__ void cp16(uint32_t s, const void* g) {
    asm volatile("cp.async.cg.shared.global [%0], [%1], 16;" :: "r"(s), "l"(g));
}
__device__ __forceinline__ void cp_commit() {
    asm volatile("cp.async.commit_group;" ::: "memory");
}
__device__ __forceinline__ void cp_wait0() {
    asm volatile("cp.async.wait_group 0;" ::: "memory");
}
__device__ __forceinline__ void ldm_x4(uint32_t* r, uint32_t addr) {
    asm volatile("ldmatrix.sync.aligned.m8n8.x4.shared.b16 {%0,%1,%2,%3}, [%4];"
        : "=r"(r[0]), "=r"(r[1]), "=r"(r[2]), "=r"(r[3]) : "r"(addr));
}
__device__ __forceinline__ void mma_f16(float* c, const uint32_t* a, const uint32_t* b) {
    asm volatile(
        "mma.sync.aligned.m16n8k16.row.col.f32.f16.f16.f32 "
        "{%0,%1,%2,%3}, {%4,%5,%6,%7}, {%8,%9}, {%0,%1,%2,%3};"
        : "+f"(c[0]), "+f"(c[1]), "+f"(c[2]), "+f"(c[3])
        : "r"(a[0]), "r"(a[1]), "r"(a[2]), "r"(a[3]), "r"(b[0]), "r"(b[1]));
}
__device__ __forceinline__ uint32_t pkh(__half a, __half b) {
    return (uint32_t)__half_as_ushort(a) | ((uint32_t)__half_as_ushort(b) << 16);
}

// ---------------------------------------------------------------------------
// Spectral norm
// ---------------------------------------------------------------------------
__global__ void spectral_kernel(const float* __restrict__ w,
                                const float* __restrict__ u)
{
    __shared__ float sv[576];
    __shared__ float red[256];
    int tid = threadIdx.x;
    float p = 0.f;
    for (int j = tid; j < 576; j += 256) {
        float s = 0.f;
        #pragma unroll 4
        for (int o = 0; o < 128; ++o) s += w[o*576 + j] * u[o];
        sv[j] = s;
        p += s * s;
    }
    red[tid] = p; __syncthreads();
    for (int s = 128; s > 0; s >>= 1) {
        if (tid < s) red[tid] += red[tid + s];
        __syncthreads();
    }
    float vinv = 1.f / (sqrtf(red[0]) + 1e-12f);
    __syncthreads();
    float q = 0.f;
    if (tid < 128) {
        float s = 0.f;
        #pragma unroll 4
        for (int j = 0; j < 576; ++j) s += w[tid*576 + j] * sv[j];
        s *= vinv;
        q = s * s;
    }
    red[tid] = q; __syncthreads();
    for (int s = 128; s > 0; s >>= 1) {
        if (tid < s) red[tid] += red[tid + s];
        __syncthreads();
    }
    if (tid == 0) g_inv_sigma = rsqrtf(red[0]);
}

// ---------------------------------------------------------------------------
// xprep: coalesced reads (w across lanes) -> smem transpose -> contiguous
// uint4 writes.  CTA = (b, h, 32-w tile); 256 threads.
// ---------------------------------------------------------------------------
__global__ __launch_bounds__(256)
void xprep_kernel(const float* __restrict__ x,
                  const float* __restrict__ mask)
{
    __shared__ uint32_t sX[32*33];

    int tid = threadIdx.x;
    int lane = tid & 31, w_ = tid >> 5;
    int w0 = blockIdx.x * 32;
    int h  = blockIdx.y;
    int b  = blockIdx.z;

    float m = mask[(b*HH + h)*WW + w0 + lane];
    #pragma unroll
    for (int k = 0; k < 4; ++k) {
        int c0 = w_*8 + 2*k;
        float v0 = x[(((size_t)b*CI + c0)*HH + h)*WW + w0 + lane] * m;
        float v1 = x[(((size_t)b*CI + c0 + 1)*HH + h)*WW + w0 + lane] * m;
        sX[(w_*4 + k)*33 + lane] = pkh(__float2half_rn(v0), __float2half_rn(v1));
    }
    __syncthreads();

    int pwl = tid >> 3, j = tid & 7;
    uint4 v;
    v.x = sX[(j*4 + 0)*33 + pwl];
    v.y = sX[(j*4 + 1)*33 + pwl];
    v.z = sX[(j*4 + 2)*33 + pwl];
    v.w = sX[(j*4 + 3)*33 + pwl];
    g_xh4[((size_t)(b*PH + h + 1))*PH*8 + (size_t)(w0 + 1 + pwl)*8 + j] = v;
}

// ---------------------------------------------------------------------------
// prep: weights [tap][oc][ch] fp16 (spectral-normalized) + gamma [oc][ch] fp16
// ---------------------------------------------------------------------------
__global__ void prep_kernel(const float* __restrict__ weight,
                            const float* __restrict__ gamma)
{
    int idx = blockIdx.x * 256 + threadIdx.x;
    if (idx < 9*128*64) {
        int c = idx & 63, o = (idx >> 6) & 127, tap = idx >> 13;
        float wv = weight[(o*64 + c)*9 + tap] * g_inv_sigma;
        g_wh[(tap*128 + o)*64 + c] = __float2half_rn(wv);
    } else if (idx < 9*128*64 + 128*128) {
        int gi = idx - 9*128*64;
        g_gh[gi] = __float2half_rn(gamma[gi]);
    }
}

// ---------------------------------------------------------------------------
// Fused Conv3x3 + partial renorm + GDN.  CTA = 256 thr, tile 128 px x 128 oc.
// Warp tile 32 px x 64 oc (4 px-warps x 2 oc-warps) -> 192 B ldmatrix per MMA.
// GDN runs as two 32x32 oc-halves to cap registers.  2 CTAs/SM.
// smem: [0, 49920)  A (3 rows x 130 px x 128B) -> later xsq (128 px x 256B)
//       [49920, 82688) B w-tap double buffer (2x16KB) -> later gamma (32KB)
//       [82688+) sRat(128), sBias(128), sBeta(128)
// ---------------------------------------------------------------------------
#define CV_AROW  16640
#define CV_B     49920
#define CV_RAT   82688
#define CV_BIAS  83200
#define CV_BETA  83712
#define CV_SMEM  84224

__global__ __launch_bounds__(256, 2)
void convgdn_mma_kernel(const float* __restrict__ bias,
                        const float* __restrict__ beta,
                        const float* __restrict__ mask)
{
    extern __shared__ unsigned char dsm[];
    uint32_t sbase = smem_u32(dsm);
    uint32_t sA = sbase;                  // also xsq
    uint32_t sB = sbase + CV_B;           // also gamma
    float* sRat  = (float*)(dsm + CV_RAT);
    float* sBias = (float*)(dsm + CV_BIAS);
    float* sBeta = (float*)(dsm + CV_BETA);

    int tid = threadIdx.x;
    int lane = tid & 31, wid = tid >> 5;  // 8 warps
    int wm = (wid & 3) * 32;              // px offset  (128/32)
    int wn = (wid >> 2) * 64;             // oc offset  (128/64)

    int t = blockIdx.x;                   // 4096
    int b = t >> 9, h = (t & 511) >> 1, q = t & 1;

    if (tid < 128) {
        sBias[tid] = bias[tid];
        sBeta[tid] = beta[tid];
    }

    // stage A: 3 rows x 130 px x 128B
    for (int i = tid; i < 3120; i += 256) {
        int r = i / 1040, rem2 = i % 1040;
        int p = rem2 >> 3, c = rem2 & 7;
        const uint4* src = g_xh4
            + ((size_t)(b*PH + h + r))*PH*8 + (size_t)(q*128 + p)*8 + c;
        cp16(sA + r*CV_AROW + p*128 + ((c ^ (p & 7)) << 4), src);
    }
    // stage B tap 0 -> buf 0
    for (int i = tid; i < 1024; i += 256) {
        int o = i >> 3, c = i & 7;
        const __half* src = g_wh + (size_t)o*64 + c*8;
        cp16(sB + o*128 + ((c ^ (o & 7)) << 4), src);
    }
    cp_commit();

    // partial-conv ratio (overlaps staging latency)
    int wq0 = q*128;
    if (tid < 128) {
        int wq = wq0 + tid;
        float s = 0.f;
        #pragma unroll
        for (int dh = -1; dh <= 1; ++dh) {
            int gh = h + dh;
            if ((unsigned)gh >= (unsigned)HH) continue;
            #pragma unroll
            for (int dw = -1; dw <= 1; ++dw) {
                int gw = wq + dw;
                if ((unsigned)gw >= (unsigned)WW) continue;
                s += mask[(b*HH + gh)*WW + gw];
            }
        }
        float ratio = s > 0.f ? 9.f / fmaxf(s, 1e-8f) : 0.f;
        sRat[tid] = ratio;
        g_ratio[(b*HH + h)*WW + wq] = ratio;
    }

    float acc[2][8][4];
    #pragma unroll
    for (int ma = 0; ma < 2; ++ma)
        #pragma unroll
        for (int nt = 0; nt < 8; ++nt)
            #pragma unroll
            for (int k = 0; k < 4; ++k) acc[ma][nt][k] = 0.f;

    for (int tap = 0; tap < 9; ++tap) {
        cp_wait0();
        __syncthreads();
        if (tap < 8) {
            int nt2 = tap + 1;
            uint32_t bu = (uint32_t)(nt2 & 1);
            for (int i = tid; i < 1024; i += 256) {
                int o = i >> 3, c = i & 7;
                const __half* src = g_wh + (size_t)(nt2*128 + o)*64 + c*8;
                cp16(sB + bu*16384 + o*128 + ((c ^ (o & 7)) << 4), src);
            }
            cp_commit();
        }
        int dh = tap / 3, dw = tap % 3;
        uint32_t abase = sA + (uint32_t)dh*CV_AROW;
        uint32_t bbase = sB + (uint32_t)(tap & 1)*16384;
        #pragma unroll
        for (int ks = 0; ks < 4; ++ks) {
            uint32_t bf[8][2];
            #pragma unroll
            for (int nb = 0; nb < 4; ++nb) {
                int n = wn + nb*16 + (lane & 7) + ((lane >> 4) << 3);
                int ch = 2*ks + ((lane >> 3) & 1);
                uint32_t r4[4];
                ldm_x4(r4, bbase + n*128 + ((ch ^ (n & 7)) << 4));
                bf[2*nb][0] = r4[0]; bf[2*nb][1] = r4[1];
                bf[2*nb+1][0] = r4[2]; bf[2*nb+1][1] = r4[3];
            }
            uint32_t a[2][4];
            #pragma unroll
            for (int ma = 0; ma < 2; ++ma) {
                int m = wm + ma*16 + (lane & 7) + ((lane >> 3) & 1)*8;
                int p = m + dw;
                int ch = 2*ks + (lane >> 4);
                ldm_x4(a[ma], abase + p*128 + ((ch ^ (p & 7)) << 4));
            }
            #pragma unroll
            for (int ma = 0; ma < 2; ++ma)
                #pragma unroll
                for (int nt = 0; nt < 8; ++nt)
                    mma_f16(acc[ma][nt], a[ma], bf[nt]);
        }
        __syncthreads();
    }

    // ---- load gamma into B region (B dead now) ----
    for (int i = tid; i < 2048; i += 256) {
        int o = i >> 4, c = i & 15;
        const __half* src = g_gh + (size_t)o*128 + c*8;
        cp16(sB + o*256 + ((c ^ (o & 7)) << 4), src);
    }
    cp_commit();

    // ---- y in regs (ratio+bias), xsq=fp16(y^2) into A region [px][256B] ----
    #pragma unroll
    for (int ma = 0; ma < 2; ++ma)
        #pragma unroll
        for (int nt = 0; nt < 8; ++nt) {
            int r  = wm + ma*16 + (lane >> 2);
            int cb = wn + nt*8 + 2*(lane & 3);
            float rt0 = sRat[r], rt8 = sRat[r + 8];
            float y0 = rt0 > 0.f ? acc[ma][nt][0]*rt0 + sBias[cb]   : 0.f;
            float y1 = rt0 > 0.f ? acc[ma][nt][1]*rt0 + sBias[cb+1] : 0.f;
            float y2 = rt8 > 0.f ? acc[ma][nt][2]*rt8 + sBias[cb]   : 0.f;
            float y3 = rt8 > 0.f ? acc[ma][nt][3]*rt8 + sBias[cb+1] : 0.f;
            acc[ma][nt][0] = y0; acc[ma][nt][1] = y1;
            acc[ma][nt][2] = y2; acc[ma][nt][3] = y3;
            uint32_t c0 = (uint32_t)(cb >> 3), e0 = (uint32_t)(cb & 7);
            uint32_t c1 = (uint32_t)((cb+1) >> 3), e1 = (uint32_t)((cb+1) & 7);
            *(__half*)(dsm + (uint32_t)r*256 + ((c0 ^ (r & 7)) << 4) + e0*2)
                = __float2half_rn(y0*y0);
            *(__half*)(dsm + (uint32_t)r*256 + ((c1 ^ (r & 7)) << 4) + e1*2)
                = __float2half_rn(y1*y1);
            *(__half*)(dsm + (uint32_t)(r+8)*256 + ((c0 ^ ((r+8) & 7)) << 4) + e0*2)
                = __float2half_rn(y2*y2);
            *(__half*)(dsm + (uint32_t)(r+8)*256 + ((c1 ^ ((r+8) & 7)) << 4) + e1*2)
                = __float2half_rn(y3*y3);
        }
    cp_wait0();
    __syncthreads();

    // ---- GDN GEMM in two 32-oc halves; write final output per half ----
    size_t gout = (size_t)b*CO*HH*WW + (size_t)h*WW + wq0;
    #pragma unroll
    for (int half = 0; half < 2; ++half) {
        int ocb = wn + half*32;
        float ac2[2][4][4];
        #pragma unroll
        for (int ma = 0; ma < 2; ++ma)
            #pragma unroll
            for (int nt = 0; nt < 4; ++nt)
                #pragma unroll
                for (int k = 0; k < 4; ++k) ac2[ma][nt][k] = 0.f;

        #pragma unroll
        for (int ks = 0; ks < 8; ++ks) {
            uint32_t a[2][4];
            #pragma unroll
            for (int ma = 0; ma < 2; ++ma) {
                int p = wm + ma*16 + (lane & 7) + ((lane >> 3) & 1)*8;
                int ch = 2*ks + (lane >> 4);
                ldm_x4(a[ma], sA + p*256 + ((ch ^ (p & 7)) << 4));
            }
            uint32_t bf[4][2];
            #pragma unroll
            for (int nb = 0; nb < 2; ++nb) {
                int n = ocb + nb*16 + (lane & 7) + ((lane >> 4) << 3);
                int ch = 2*ks + ((lane >> 3) & 1);
                uint32_t r4[4];
                ldm_x4(r4, sB + n*256 + ((ch ^ (n & 7)) << 4));
                bf[2*nb][0] = r4[0]; bf[2*nb][1] = r4[1];
                bf[2*nb+1][0] = r4[2]; bf[2*nb+1][1] = r4[3];
            }
            #pragma unroll
            for (int ma = 0; ma < 2; ++ma)
                #pragma unroll
                for (int nt = 0; nt < 4; ++nt)
                    mma_f16(ac2[ma][nt], a[ma], bf[nt]);
        }

        #pragma unroll
        for (int ma = 0; ma < 2; ++ma)
            #pragma unroll
            for (int nt = 0; nt < 4; ++nt) {
                int gnt = half*4 + nt;
                int r  = wm + ma*16 + (lane >> 2);
                int cb = ocb + nt*8 + 2*(lane & 3);
                float be0 = sBeta[cb], be1 = sBeta[cb + 1];
                g_x[gout + (size_t)cb*(HH*WW) + r] =
                    acc[ma][gnt][0] * rsqrtf(be0 + ac2[ma][nt][0]);
                g_x[gout + (size_t)(cb+1)*(HH*WW) + r] =
                    acc[ma][gnt][1] * rsqrtf(be1 + ac2[ma][nt][1]);
                g_x[gout + (size_t)cb*(HH*WW) + r + 8] =
                    acc[ma][gnt][2] * rsqrtf(be0 + ac2[ma][nt][2]);
                g_x[gout + (size_t)(cb+1)*(HH*WW) + r + 8] =
                    acc[ma][gnt][3] * rsqrtf(be1 + ac2[ma][nt][3]);
            }
    }
}

// ---------------------------------------------------------------------------
// Fused 2D DWT (CDF 9/7 analysis), 32x32 output tile (72x72 input, halo 1.27x)
// ---------------------------------------------------------------------------
__global__ __launch_bounds__(256)
void dwt_kernel(float* __restrict__ out)
{
    __shared__ float sT[72][76];
    __shared__ float sLo[32][76];
    __shared__ float sHi[32][76];

    int tid = threadIdx.x;
    int z = blockIdx.z;
    int hb = blockIdx.y * 32, wb = blockIdx.x * 32;   // output coords
    const float* src = g_x + (size_t)z * HH * WW;

    for (int i = tid; i < 72*72; i += 256) {
        int r = i / 72, cc = i % 72;
        int gr = refl(2*hb - 4 + r, HH);
        int gc = refl(2*wb - 4 + cc, WW);
        sT[r][cc] = src[gr*WW + gc];
    }
    __syncthreads();

    for (int i = tid; i < 32*72; i += 256) {
        int r = i / 72, cc = i % 72;
        float lo = 0.f, hi = 0.f;
        #pragma unroll
        for (int k = 0; k < 9; ++k) lo += c_h0[k] * sT[2*r + k][cc];
        #pragma unroll
        for (int k = 0; k < 7; ++k) hi += c_h1[k] * sT[2*r + k + 1][cc];
        sLo[r][cc] = lo;
        sHi[r][cc] = hi;
    }
    __syncthreads();

    for (int i = tid; i < 32*32; i += 256) {
        int r = i / 32, co = i % 32;
        float ll = 0.f, lh = 0.f, hl = 0.f, hh = 0.f;
        #pragma unroll
        for (int k = 0; k < 9; ++k) {
            ll += c_h0[k] * sLo[r][2*co + k];
            hl += c_h0[k] * sHi[r][2*co + k];
        }
        #pragma unroll
        for (int k = 0; k < 7; ++k) {
            lh += c_h1[k] * sLo[r][2*co + k + 1];
            hh += c_h1[k] * sHi[r][2*co + k + 1];
        }
        size_t idx = (size_t)z*16384 + (size_t)(hb + r)*128 + (wb + co);
        out[OFF_LL + idx] = ll;
        out[OFF_LH + idx] = lh;
        out[OFF_HL + idx] = hl;
        out[OFF_HH + idx] = hh;
    }
}

// ---------------------------------------------------------------------------
// Mask DWT: OR over reflected 9/7 windows
// ---------------------------------------------------------------------------
__global__ void maskdwt_kernel(float* __restrict__ out)
{
    int idx = blockIdx.x * 256 + threadIdx.x;
    if (idx >= BB*128*128) return;
    int b = idx >> 14, rem = idx & 16383;
    int ho = rem >> 7, wo = rem & 127;

    bool mll = false, mlh = false, mhl = false, mhh = false;
    #pragma unroll
    for (int dr = -4; dr <= 4; ++dr) {
        int gr = refl(2*ho + dr, HH);
        bool row9 = false, row7 = false;
        #pragma unroll
        for (int dc = -4; dc <= 4; ++dc) {
            int gc = refl(2*wo + dc, WW);
            bool v = g_ratio[(b*HH + gr)*WW + gc] > 0.f;
            row9 |= v;
            if (dc >= -3 && dc <= 3) row7 |= v;
        }
        mll |= row9;
        mlh |= row7;
        if (dr >= -3 && dr <= 3) { mhl |= row9; mhh |= row7; }
    }
    out[OFF_MLL + idx] = mll ? 1.f : 0.f;
    out[OFF_MLH + idx] = mlh ? 1.f : 0.f;
    out[OFF_MHL + idx] = mhl ? 1.f : 0.f;
    out[OFF_MHH + idx] = mhh ? 1.f : 0.f;
}

// ---------------------------------------------------------------------------
extern "C" void kernel_launch(void* const* d_in, const int* in_sizes, int n_in,
                              void* d_out, int out_size)
{
    const float* tensor = (const float*)d_in[0];
    const float* mask   = (const float*)d_in[1];
    const float* weight = (const float*)d_in[2];
    const float* bias   = (const float*)d_in[3];
    const float* u      = (const float*)d_in[4];
    const float* beta   = (const float*)d_in[5];
    const float* gamma  = (const float*)d_in[6];
    float* out = (float*)d_out;

    cudaFuncSetAttribute(convgdn_mma_kernel,
                         cudaFuncAttributeMaxDynamicSharedMemorySize, CV_SMEM);

    spectral_kernel<<<1, 256>>>(weight, u);                          // 0
    xprep_kernel<<<dim3(8, 256, 8), 256>>>(tensor, mask);            // 1
    prep_kernel<<<(9*128*64 + 128*128 + 255)/256, 256>>>(weight, gamma); // 2
    convgdn_mma_kernel<<<4096, 256, CV_SMEM>>>(bias, beta, mask);    // 3 (profiled)
    dwt_kernel<<<dim3(4, 4, BB*CO), 256>>>(out);                     // 4
    maskdwt_kernel<<<(BB*128*128 + 255)/256, 256>>>(out);            // 5
}

// round 14
// speedup vs baseline: 1.2935x; 1.2935x over previous
#include <cuda_runtime.h>
#include <cuda_fp16.h>
#include <math.h>
#include <cstdint>

#define BB 8
#define CI 64
#define CO 128
#define HH 256
#define WW 256

#define SUB (BB*CO*128*128)
#define MSK (BB*128*128)
#define OFF_LL  0
#define OFF_MLL (SUB)
#define OFF_LH  (SUB + MSK)
#define OFF_HL  (2*SUB + MSK)
#define OFF_HH  (3*SUB + MSK)
#define OFF_MLH (4*SUB + MSK)
#define OFF_MHL (4*SUB + 2*MSK)
#define OFF_MHH (4*SUB + 3*MSK)

#define PH 258

// Scratch
__device__ __half g_x[(size_t)BB*CO*HH*WW];   // GDN output (DWT input), fp16
__device__ float g_ratio[BB*HH*WW];
__device__ float g_inv_sigma;
// zero-initialized; xprep writes interior only, so borders stay zero forever
__device__ uint4 g_xh4[(size_t)BB*PH*PH*8];   // padded NHWC fp16 of x*mask
__device__ __half g_wh[9*128*64];             // [tap][oc][ch] fp16 (spectral-normalized)
__device__ __half g_gh[128*128];              // gamma [oc][ch] fp16

__constant__ float c_h0[9] = {
    0.026748757410810f, -0.016864118442875f, -0.078223266528990f,
    0.266864118442875f,  0.602949018236360f,  0.266864118442875f,
   -0.078223266528990f, -0.016864118442875f,  0.026748757410810f};
__constant__ float c_h1[7] = {
    0.091271763114250f, -0.057543526228500f, -0.591271763114250f,
    1.115087052457000f, -0.591271763114250f, -0.057543526228500f,
    0.091271763114250f};

__device__ __forceinline__ int refl(int i, int n) {
    return i < 0 ? -i : (i >= n ? 2*n - 2 - i : i);
}
__device__ __forceinline__ uint32_t smem_u32(const void* p) {
    uint32_t a;
    asm("{ .reg .u64 t; cvta.to.shared.u64 t, %1; cvt.u32.u64 %0, t; }" : "=r"(a) : "l"(p));
    return a;
}
__device__ __forceinline__ void cp16(uint32_t s, const void* g) {
    asm volatile("cp.async.cg.shared.global [%0], [%1], 16;" :: "r"(s), "l"(g));
}
__device__ __forceinline__ void cp_commit() {
    asm volatile("cp.async.commit_group;" ::: "memory");
}
__device__ __forceinline__ void cp_wait0() {
    asm volatile("cp.async.wait_group 0;" ::: "memory");
}
__device__ __forceinline__ void ldm_x4(uint32_t* r, uint32_t addr) {
    asm volatile("ldmatrix.sync.aligned.m8n8.x4.shared.b16 {%0,%1,%2,%3}, [%4];"
        : "=r"(r[0]), "=r"(r[1]), "=r"(r[2]), "=r"(r[3]) : "r"(addr));
}
__device__ __forceinline__ void mma_f16(float* c, const uint32_t* a, const uint32_t* b) {
    asm volatile(
        "mma.sync.aligned.m16n8k16.row.col.f32.f16.f16.f32 "
        "{%0,%1,%2,%3}, {%4,%5,%6,%7}, {%8,%9}, {%0,%1,%2,%3};"
        : "+f"(c[0]), "+f"(c[1]), "+f"(c[2]), "+f"(c[3])
        : "r"(a[0]), "r"(a[1]), "r"(a[2]), "r"(a[3]), "r"(b[0]), "r"(b[1]));
}
__device__ __forceinline__ uint32_t pkh(__half a, __half b) {
    return (uint32_t)__half_as_ushort(a) | ((uint32_t)__half_as_ushort(b) << 16);
}

// ---------------------------------------------------------------------------
// Spectral norm
// ---------------------------------------------------------------------------
__global__ void spectral_kernel(const float* __restrict__ w,
                                const float* __restrict__ u)
{
    __shared__ float sv[576];
    __shared__ float red[256];
    int tid = threadIdx.x;
    float p = 0.f;
    for (int j = tid; j < 576; j += 256) {
        float s = 0.f;
        #pragma unroll 4
        for (int o = 0; o < 128; ++o) s += w[o*576 + j] * u[o];
        sv[j] = s;
        p += s * s;
    }
    red[tid] = p; __syncthreads();
    for (int s = 128; s > 0; s >>= 1) {
        if (tid < s) red[tid] += red[tid + s];
        __syncthreads();
    }
    float vinv = 1.f / (sqrtf(red[0]) + 1e-12f);
    __syncthreads();
    float q = 0.f;
    if (tid < 128) {
        float s = 0.f;
        #pragma unroll 4
        for (int j = 0; j < 576; ++j) s += w[tid*576 + j] * sv[j];
        s *= vinv;
        q = s * s;
    }
    red[tid] = q; __syncthreads();
    for (int s = 128; s > 0; s >>= 1) {
        if (tid < s) red[tid] += red[tid + s];
        __syncthreads();
    }
    if (tid == 0) g_inv_sigma = rsqrtf(red[0]);
}

// ---------------------------------------------------------------------------
// xprep: coalesced reads (w across lanes) -> smem transpose -> contiguous
// uint4 writes.  CTA = (b, h, 32-w tile); 256 threads.
// ---------------------------------------------------------------------------
__global__ __launch_bounds__(256)
void xprep_kernel(const float* __restrict__ x,
                  const float* __restrict__ mask)
{
    __shared__ uint32_t sX[32*33];

    int tid = threadIdx.x;
    int lane = tid & 31, w_ = tid >> 5;
    int w0 = blockIdx.x * 32;
    int h  = blockIdx.y;
    int b  = blockIdx.z;

    float m = mask[(b*HH + h)*WW + w0 + lane];
    #pragma unroll
    for (int k = 0; k < 4; ++k) {
        int c0 = w_*8 + 2*k;
        float v0 = x[(((size_t)b*CI + c0)*HH + h)*WW + w0 + lane] * m;
        float v1 = x[(((size_t)b*CI + c0 + 1)*HH + h)*WW + w0 + lane] * m;
        sX[(w_*4 + k)*33 + lane] = pkh(__float2half_rn(v0), __float2half_rn(v1));
    }
    __syncthreads();

    int pwl = tid >> 3, j = tid & 7;
    uint4 v;
    v.x = sX[(j*4 + 0)*33 + pwl];
    v.y = sX[(j*4 + 1)*33 + pwl];
    v.z = sX[(j*4 + 2)*33 + pwl];
    v.w = sX[(j*4 + 3)*33 + pwl];
    g_xh4[((size_t)(b*PH + h + 1))*PH*8 + (size_t)(w0 + 1 + pwl)*8 + j] = v;
}

// ---------------------------------------------------------------------------
// prep: weights [tap][oc][ch] fp16 (spectral-normalized) + gamma [oc][ch] fp16
// ---------------------------------------------------------------------------
__global__ void prep_kernel(const float* __restrict__ weight,
                            const float* __restrict__ gamma)
{
    int idx = blockIdx.x * 256 + threadIdx.x;
    if (idx < 9*128*64) {
        int c = idx & 63, o = (idx >> 6) & 127, tap = idx >> 13;
        float wv = weight[(o*64 + c)*9 + tap] * g_inv_sigma;
        g_wh[(tap*128 + o)*64 + c] = __float2half_rn(wv);
    } else if (idx < 9*128*64 + 128*128) {
        int gi = idx - 9*128*64;
        g_gh[gi] = __float2half_rn(gamma[gi]);
    }
}

// ---------------------------------------------------------------------------
// Fused Conv3x3 (single-pass fp16 implicit GEMM) + partial renorm + GDN
// CTA = 256 thr, tile 64 px x 128 oc, warp tile 32x32, 2 CTAs/SM.  (R11 cfg)
// smem: [0, 25344)  A (3 rows x 66 px x 128B) -> later xsq (64 px x 256B)
//       [25344, 58112) B w-tap double buffer (2x16KB) -> later gamma (32KB)
//       [58112+) sRat(64), sBias(128), sBeta(128)
// ---------------------------------------------------------------------------
#define CV_AROW  8448
#define CV_B     25344
#define CV_RAT   58112
#define CV_BIAS  58368
#define CV_BETA  58880
#define CV_SMEM  59392

__global__ __launch_bounds__(256, 2)
void convgdn_mma_kernel(const float* __restrict__ bias,
                        const float* __restrict__ beta,
                        const float* __restrict__ mask)
{
    extern __shared__ unsigned char dsm[];
    uint32_t sbase = smem_u32(dsm);
    uint32_t sA = sbase;                  // also xsq
    uint32_t sB = sbase + CV_B;           // also gamma
    float* sRat  = (float*)(dsm + CV_RAT);
    float* sBias = (float*)(dsm + CV_BIAS);
    float* sBeta = (float*)(dsm + CV_BETA);

    int tid = threadIdx.x;
    int lane = tid & 31, wid = tid >> 5;  // 8 warps
    int wm = (wid & 1) * 32;              // px offset (64/32)
    int wn = (wid >> 1) * 32;             // oc offset (128/32)

    int t = blockIdx.x;                   // 8192
    int b = t >> 10, rem = t & 1023;
    int h = rem >> 2, q = rem & 3;

    if (tid < 128) {
        sBias[tid] = bias[tid];
        sBeta[tid] = beta[tid];
    }

    // stage A: 3 rows x 66 px x 128B
    for (int i = tid; i < 1584; i += 256) {
        int r = i / 528, rem2 = i % 528;
        int p = rem2 >> 3, c = rem2 & 7;
        const uint4* src = g_xh4
            + ((size_t)(b*PH + h + r))*PH*8 + (size_t)(q*64 + p)*8 + c;
        cp16(sA + r*CV_AROW + p*128 + ((c ^ (p & 7)) << 4), src);
    }
    // stage B tap 0 -> buf 0
    for (int i = tid; i < 1024; i += 256) {
        int o = i >> 3, c = i & 7;
        const __half* src = g_wh + (size_t)o*64 + c*8;
        cp16(sB + o*128 + ((c ^ (o & 7)) << 4), src);
    }
    cp_commit();

    // partial-conv ratio (overlaps with staging latency)
    int wq0 = q*64;
    if (tid < 64) {
        int wq = wq0 + tid;
        float s = 0.f;
        #pragma unroll
        for (int dh = -1; dh <= 1; ++dh) {
            int gh = h + dh;
            if ((unsigned)gh >= (unsigned)HH) continue;
            #pragma unroll
            for (int dw = -1; dw <= 1; ++dw) {
                int gw = wq + dw;
                if ((unsigned)gw >= (unsigned)WW) continue;
                s += mask[(b*HH + gh)*WW + gw];
            }
        }
        float ratio = s > 0.f ? 9.f / fmaxf(s, 1e-8f) : 0.f;
        sRat[tid] = ratio;
        g_ratio[(b*HH + h)*WW + wq] = ratio;
    }

    float acc[2][4][4];
    #pragma unroll
    for (int ma = 0; ma < 2; ++ma)
        #pragma unroll
        for (int nt = 0; nt < 4; ++nt)
            #pragma unroll
            for (int k = 0; k < 4; ++k) acc[ma][nt][k] = 0.f;

    for (int tap = 0; tap < 9; ++tap) {
        cp_wait0();
        __syncthreads();
        if (tap < 8) {
            int nt2 = tap + 1;
            uint32_t bu = (uint32_t)(nt2 & 1);
            for (int i = tid; i < 1024; i += 256) {
                int o = i >> 3, c = i & 7;
                const __half* src = g_wh + (size_t)(nt2*128 + o)*64 + c*8;
                cp16(sB + bu*16384 + o*128 + ((c ^ (o & 7)) << 4), src);
            }
            cp_commit();
        }
        int dh = tap / 3, dw = tap % 3;
        uint32_t abase = sA + (uint32_t)dh*CV_AROW;
        uint32_t bbase = sB + (uint32_t)(tap & 1)*16384;
        #pragma unroll
        for (int ks = 0; ks < 4; ++ks) {
            uint32_t bf[4][2];
            #pragma unroll
            for (int nb = 0; nb < 2; ++nb) {
                int n = wn + nb*16 + (lane & 7) + ((lane >> 4) << 3);
                int ch = 2*ks + ((lane >> 3) & 1);
                uint32_t r4[4];
                ldm_x4(r4, bbase + n*128 + ((ch ^ (n & 7)) << 4));
                bf[2*nb][0] = r4[0]; bf[2*nb][1] = r4[1];
                bf[2*nb+1][0] = r4[2]; bf[2*nb+1][1] = r4[3];
            }
            uint32_t a[2][4];
            #pragma unroll
            for (int ma = 0; ma < 2; ++ma) {
                int m = wm + ma*16 + (lane & 7) + ((lane >> 3) & 1)*8;
                int p = m + dw;
                int ch = 2*ks + (lane >> 4);
                ldm_x4(a[ma], abase + p*128 + ((ch ^ (p & 7)) << 4));
            }
            #pragma unroll
            for (int ma = 0; ma < 2; ++ma)
                #pragma unroll
                for (int nt = 0; nt < 4; ++nt)
                    mma_f16(acc[ma][nt], a[ma], bf[nt]);
        }
        __syncthreads();
    }

    // ---- load gamma into B region (B dead now) ----
    for (int i = tid; i < 2048; i += 256) {
        int o = i >> 4, c = i & 15;
        const __half* src = g_gh + (size_t)o*128 + c*8;
        cp16(sB + o*256 + ((c ^ (o & 7)) << 4), src);
    }
    cp_commit();

    // ---- y in regs (ratio+bias), xsq=fp16(y^2) into A region [px][256B] ----
    #pragma unroll
    for (int ma = 0; ma < 2; ++ma)
        #pragma unroll
        for (int nt = 0; nt < 4; ++nt) {
            int r  = wm + ma*16 + (lane >> 2);
            int cb = wn + nt*8 + 2*(lane & 3);
            float rt0 = sRat[r], rt8 = sRat[r + 8];
            float y0 = rt0 > 0.f ? acc[ma][nt][0]*rt0 + sBias[cb]   : 0.f;
            float y1 = rt0 > 0.f ? acc[ma][nt][1]*rt0 + sBias[cb+1] : 0.f;
            float y2 = rt8 > 0.f ? acc[ma][nt][2]*rt8 + sBias[cb]   : 0.f;
            float y3 = rt8 > 0.f ? acc[ma][nt][3]*rt8 + sBias[cb+1] : 0.f;
            acc[ma][nt][0] = y0; acc[ma][nt][1] = y1;
            acc[ma][nt][2] = y2; acc[ma][nt][3] = y3;
            uint32_t c0 = (uint32_t)(cb >> 3), e0 = (uint32_t)(cb & 7);
            uint32_t c1 = (uint32_t)((cb+1) >> 3), e1 = (uint32_t)((cb+1) & 7);
            *(__half*)(dsm + (uint32_t)r*256 + ((c0 ^ (r & 7)) << 4) + e0*2)
                = __float2half_rn(y0*y0);
            *(__half*)(dsm + (uint32_t)r*256 + ((c1 ^ (r & 7)) << 4) + e1*2)
                = __float2half_rn(y1*y1);
            *(__half*)(dsm + (uint32_t)(r+8)*256 + ((c0 ^ ((r+8) & 7)) << 4) + e0*2)
                = __float2half_rn(y2*y2);
            *(__half*)(dsm + (uint32_t)(r+8)*256 + ((c1 ^ ((r+8) & 7)) << 4) + e1*2)
                = __float2half_rn(y3*y3);
        }
    cp_wait0();
    __syncthreads();

    // ---- GDN GEMM: D2[px][oc] = xsq[px][ch] @ gamma[oc][ch]^T ----
    float ac2[2][4][4];
    #pragma unroll
    for (int ma = 0; ma < 2; ++ma)
        #pragma unroll
        for (int nt = 0; nt < 4; ++nt)
            #pragma unroll
            for (int k = 0; k < 4; ++k) ac2[ma][nt][k] = 0.f;

    #pragma unroll
    for (int ks = 0; ks < 8; ++ks) {
        uint32_t a[2][4];
        #pragma unroll
        for (int ma = 0; ma < 2; ++ma) {
            int p = wm + ma*16 + (lane & 7) + ((lane >> 3) & 1)*8;
            int ch = 2*ks + (lane >> 4);
            ldm_x4(a[ma], sA + p*256 + ((ch ^ (p & 7)) << 4));
        }
        uint32_t bf[4][2];
        #pragma unroll
        for (int nb = 0; nb < 2; ++nb) {
            int n = wn + nb*16 + (lane & 7) + ((lane >> 4) << 3);
            int ch = 2*ks + ((lane >> 3) & 1);
            uint32_t r4[4];
            ldm_x4(r4, sB + n*256 + ((ch ^ (n & 7)) << 4));
            bf[2*nb][0] = r4[0]; bf[2*nb][1] = r4[1];
            bf[2*nb+1][0] = r4[2]; bf[2*nb+1][1] = r4[3];
        }
        #pragma unroll
        for (int ma = 0; ma < 2; ++ma)
            #pragma unroll
            for (int nt = 0; nt < 4; ++nt)
                mma_f16(ac2[ma][nt], a[ma], bf[nt]);
    }

    // ---- final: g_x[oc][px] (fp16) = y * rsqrt(beta + D2) ----
    size_t gout = (size_t)b*CO*HH*WW + (size_t)h*WW + wq0;
    #pragma unroll
    for (int ma = 0; ma < 2; ++ma)
        #pragma unroll
        for (int nt = 0; nt < 4; ++nt) {
            int r  = wm + ma*16 + (lane >> 2);
            int cb = wn + nt*8 + 2*(lane & 3);
            float be0 = sBeta[cb], be1 = sBeta[cb + 1];
            g_x[gout + (size_t)cb*(HH*WW) + r] =
                __float2half_rn(acc[ma][nt][0] * rsqrtf(be0 + ac2[ma][nt][0]));
            g_x[gout + (size_t)(cb+1)*(HH*WW) + r] =
                __float2half_rn(acc[ma][nt][1] * rsqrtf(be1 + ac2[ma][nt][1]));
            g_x[gout + (size_t)cb*(HH*WW) + r + 8] =
                __float2half_rn(acc[ma][nt][2] * rsqrtf(be0 + ac2[ma][nt][2]));
            g_x[gout + (size_t)(cb+1)*(HH*WW) + r + 8] =
                __float2half_rn(acc[ma][nt][3] * rsqrtf(be1 + ac2[ma][nt][3]));
        }
}

// ---------------------------------------------------------------------------
// Fused 2D DWT (CDF 9/7 analysis), fp16 input  (R11 16x32 tiling)
// ---------------------------------------------------------------------------
__global__ __launch_bounds__(256)
void dwt_kernel(float* __restrict__ out)
{
    __shared__ float sT[40][72];
    __shared__ float sLo[16][72];
    __shared__ float sHi[16][72];

    int tid = threadIdx.x;
    int z = blockIdx.z;
    int hb = blockIdx.y * 16, wb = blockIdx.x * 32;
    const __half* src = g_x + (size_t)z * HH * WW;

    for (int i = tid; i < 40*72; i += 256) {
        int r = i / 72, cc = i % 72;
        int gr = refl(2*hb - 4 + r, HH);
        int gc = refl(2*wb - 4 + cc, WW);
        sT[r][cc] = __half2float(src[gr*WW + gc]);
    }
    __syncthreads();

    for (int i = tid; i < 16*72; i += 256) {
        int r = i / 72, cc = i % 72;
        float lo = 0.f, hi = 0.f;
        #pragma unroll
        for (int k = 0; k < 9; ++k) lo += c_h0[k] * sT[2*r + k][cc];
        #pragma unroll
        for (int k = 0; k < 7; ++k) hi += c_h1[k] * sT[2*r + k + 1][cc];
        sLo[r][cc] = lo;
        sHi[r][cc] = hi;
    }
    __syncthreads();

    for (int i = tid; i < 16*32; i += 256) {
        int r = i / 32, co = i % 32;
        float ll = 0.f, lh = 0.f, hl = 0.f, hh = 0.f;
        #pragma unroll
        for (int k = 0; k < 9; ++k) {
            ll += c_h0[k] * sLo[r][2*co + k];
            hl += c_h0[k] * sHi[r][2*co + k];
        }
        #pragma unroll
        for (int k = 0; k < 7; ++k) {
            lh += c_h1[k] * sLo[r][2*co + k + 1];
            hh += c_h1[k] * sHi[r][2*co + k + 1];
        }
        size_t idx = (size_t)z*16384 + (size_t)(hb + r)*128 + (wb + co);
        out[OFF_LL + idx] = ll;
        out[OFF_LH + idx] = lh;
        out[OFF_HL + idx] = hl;
        out[OFF_HH + idx] = hh;
    }
}

// ---------------------------------------------------------------------------
// Mask DWT: OR over reflected 9/7 windows
// ---------------------------------------------------------------------------
__global__ void maskdwt_kernel(float* __restrict__ out)
{
    int idx = blockIdx.x * 256 + threadIdx.x;
    if (idx >= BB*128*128) return;
    int b = idx >> 14, rem = idx & 16383;
    int ho = rem >> 7, wo = rem & 127;

    bool mll = false, mlh = false, mhl = false, mhh = false;
    #pragma unroll
    for (int dr = -4; dr <= 4; ++dr) {
        int gr = refl(2*ho + dr, HH);
        bool row9 = false, row7 = false;
        #pragma unroll
        for (int dc = -4; dc <= 4; ++dc) {
            int gc = refl(2*wo + dc, WW);
            bool v = g_ratio[(b*HH + gr)*WW + gc] > 0.f;
            row9 |= v;
            if (dc >= -3 && dc <= 3) row7 |= v;
        }
        mll |= row9;
        mlh |= row7;
        if (dr >= -3 && dr <= 3) { mhl |= row9; mhh |= row7; }
    }
    out[OFF_MLL + idx] = mll ? 1.f : 0.f;
    out[OFF_MLH + idx] = mlh ? 1.f : 0.f;
    out[OFF_MHL + idx] = mhl ? 1.f : 0.f;
    out[OFF_MHH + idx] = mhh ? 1.f : 0.f;
}

// ---------------------------------------------------------------------------
extern "C" void kernel_launch(void* const* d_in, const int* in_sizes, int n_in,
                              void* d_out, int out_size)
{
    const float* tensor = (const float*)d_in[0];
    const float* mask   = (const float*)d_in[1];
    const float* weight = (const float*)d_in[2];
    const float* bias   = (const float*)d_in[3];
    const float* u      = (const float*)d_in[4];
    const float* beta   = (const float*)d_in[5];
    const float* gamma  = (const float*)d_in[6];
    float* out = (float*)d_out;

    cudaFuncSetAttribute(convgdn_mma_kernel,
                         cudaFuncAttributeMaxDynamicSharedMemorySize, CV_SMEM);

    spectral_kernel<<<1, 256>>>(weight, u);                          // 0
    xprep_kernel<<<dim3(8, 256, 8), 256>>>(tensor, mask);            // 1
    prep_kernel<<<(9*128*64 + 128*128 + 255)/256, 256>>>(weight, gamma); // 2
    convgdn_mma_kernel<<<8192, 256, CV_SMEM>>>(bias, beta, mask);    // 3 (profiled)
    dwt_kernel<<<dim3(4, 8, BB*CO), 256>>>(out);                     // 4
    maskdwt_kernel<<<(BB*128*128 + 255)/256, 256>>>(out);            // 5
}

// round 15
// speedup vs baseline: 1.3244x; 1.0239x over previous
#include <cuda_runtime.h>
#include <cuda_fp16.h>
#include <math.h>
#include <cstdint>

#define BB 8
#define CI 64
#define CO 128
#define HH 256
#define WW 256

#define SUB (BB*CO*128*128)
#define MSK (BB*128*128)
#define OFF_LL  0
#define OFF_MLL (SUB)
#define OFF_LH  (SUB + MSK)
#define OFF_HL  (2*SUB + MSK)
#define OFF_HH  (3*SUB + MSK)
#define OFF_MLH (4*SUB + MSK)
#define OFF_MHL (4*SUB + 2*MSK)
#define OFF_MHH (4*SUB + 3*MSK)

#define PH 258

// Scratch
__device__ __half g_x[(size_t)BB*CO*HH*WW];   // GDN output (DWT input), fp16
__device__ float g_ratio[BB*HH*WW];
__device__ float g_inv_sigma;
// zero-initialized; xprep writes interior only, so borders stay zero forever
__device__ uint4 g_xh4[(size_t)BB*PH*PH*8];   // padded NHWC fp16 of x*mask
__device__ __half g_wh[9*128*64];             // [tap][oc][ch] fp16 (spectral-normalized)
__device__ __half g_gh[128*128];              // gamma [oc][ch] fp16

__constant__ float c_h0[9] = {
    0.026748757410810f, -0.016864118442875f, -0.078223266528990f,
    0.266864118442875f,  0.602949018236360f,  0.266864118442875f,
   -0.078223266528990f, -0.016864118442875f,  0.026748757410810f};
__constant__ float c_h1[7] = {
    0.091271763114250f, -0.057543526228500f, -0.591271763114250f,
    1.115087052457000f, -0.591271763114250f, -0.057543526228500f,
    0.091271763114250f};

__device__ __forceinline__ int refl(int i, int n) {
    return i < 0 ? -i : (i >= n ? 2*n - 2 - i : i);
}
__device__ __forceinline__ uint32_t smem_u32(const void* p) {
    uint32_t a;
    asm("{ .reg .u64 t; cvta.to.shared.u64 t, %1; cvt.u32.u64 %0, t; }" : "=r"(a) : "l"(p));
    return a;
}
__device__ __forceinline__ void cp16(uint32_t s, const void* g) {
    asm volatile("cp.async.cg.shared.global [%0], [%1], 16;" :: "r"(s), "l"(g));
}
__device__ __forceinline__ void cp_commit() {
    asm volatile("cp.async.commit_group;" ::: "memory");
}
__device__ __forceinline__ void cp_wait0() {
    asm volatile("cp.async.wait_group 0;" ::: "memory");
}
__device__ __forceinline__ void ldm_x4(uint32_t* r, uint32_t addr) {
    asm volatile("ldmatrix.sync.aligned.m8n8.x4.shared.b16 {%0,%1,%2,%3}, [%4];"
        : "=r"(r[0]), "=r"(r[1]), "=r"(r[2]), "=r"(r[3]) : "r"(addr));
}
__device__ __forceinline__ void mma_f16(float* c, const uint32_t* a, const uint32_t* b) {
    asm volatile(
        "mma.sync.aligned.m16n8k16.row.col.f32.f16.f16.f32 "
        "{%0,%1,%2,%3}, {%4,%5,%6,%7}, {%8,%9}, {%0,%1,%2,%3};"
        : "+f"(c[0]), "+f"(c[1]), "+f"(c[2]), "+f"(c[3])
        : "r"(a[0]), "r"(a[1]), "r"(a[2]), "r"(a[3]), "r"(b[0]), "r"(b[1]));
}
__device__ __forceinline__ uint32_t pkh(__half a, __half b) {
    return (uint32_t)__half_as_ushort(a) | ((uint32_t)__half_as_ushort(b) << 16);
}

// ---------------------------------------------------------------------------
// Spectral norm
// ---------------------------------------------------------------------------
__global__ void spectral_kernel(const float* __restrict__ w,
                                const float* __restrict__ u)
{
    __shared__ float sv[576];
    __shared__ float red[256];
    int tid = threadIdx.x;
    float p = 0.f;
    for (int j = tid; j < 576; j += 256) {
        float s = 0.f;
        #pragma unroll 4
        for (int o = 0; o < 128; ++o) s += w[o*576 + j] * u[o];
        sv[j] = s;
        p += s * s;
    }
    red[tid] = p; __syncthreads();
    for (int s = 128; s > 0; s >>= 1) {
        if (tid < s) red[tid] += red[tid + s];
        __syncthreads();
    }
    float vinv = 1.f / (sqrtf(red[0]) + 1e-12f);
    __syncthreads();
    float q = 0.f;
    if (tid < 128) {
        float s = 0.f;
        #pragma unroll 4
        for (int j = 0; j < 576; ++j) s += w[tid*576 + j] * sv[j];
        s *= vinv;
        q = s * s;
    }
    red[tid] = q; __syncthreads();
    for (int s = 128; s > 0; s >>= 1) {
        if (tid < s) red[tid] += red[tid + s];
        __syncthreads();
    }
    if (tid == 0) g_inv_sigma = rsqrtf(red[0]);
}

// ---------------------------------------------------------------------------
// xprep: coalesced reads (w across lanes) -> smem transpose -> contiguous
// uint4 writes.  CTA = (b, h, 32-w tile); 256 threads.
// ---------------------------------------------------------------------------
__global__ __launch_bounds__(256)
void xprep_kernel(const float* __restrict__ x,
                  const float* __restrict__ mask)
{
    __shared__ uint32_t sX[32*33];

    int tid = threadIdx.x;
    int lane = tid & 31, w_ = tid >> 5;
    int w0 = blockIdx.x * 32;
    int h  = blockIdx.y;
    int b  = blockIdx.z;

    float m = mask[(b*HH + h)*WW + w0 + lane];
    #pragma unroll
    for (int k = 0; k < 4; ++k) {
        int c0 = w_*8 + 2*k;
        float v0 = x[(((size_t)b*CI + c0)*HH + h)*WW + w0 + lane] * m;
        float v1 = x[(((size_t)b*CI + c0 + 1)*HH + h)*WW + w0 + lane] * m;
        sX[(w_*4 + k)*33 + lane] = pkh(__float2half_rn(v0), __float2half_rn(v1));
    }
    __syncthreads();

    int pwl = tid >> 3, j = tid & 7;
    uint4 v;
    v.x = sX[(j*4 + 0)*33 + pwl];
    v.y = sX[(j*4 + 1)*33 + pwl];
    v.z = sX[(j*4 + 2)*33 + pwl];
    v.w = sX[(j*4 + 3)*33 + pwl];
    g_xh4[((size_t)(b*PH + h + 1))*PH*8 + (size_t)(w0 + 1 + pwl)*8 + j] = v;
}

// ---------------------------------------------------------------------------
// prep: weights [tap][oc][ch] fp16 (spectral-normalized) + gamma [oc][ch] fp16
// ---------------------------------------------------------------------------
__global__ void prep_kernel(const float* __restrict__ weight,
                            const float* __restrict__ gamma)
{
    int idx = blockIdx.x * 256 + threadIdx.x;
    if (idx < 9*128*64) {
        int c = idx & 63, o = (idx >> 6) & 127, tap = idx >> 13;
        float wv = weight[(o*64 + c)*9 + tap] * g_inv_sigma;
        g_wh[(tap*128 + o)*64 + c] = __float2half_rn(wv);
    } else if (idx < 9*128*64 + 128*128) {
        int gi = idx - 9*128*64;
        g_gh[gi] = __float2half_rn(gamma[gi]);
    }
}

// ---------------------------------------------------------------------------
// Fused Conv3x3 (single-pass fp16 implicit GEMM) + partial renorm + GDN
// CTA = 256 thr, tile 64 px x 128 oc, warp tile 32x32, 2 CTAs/SM.
// Triple-buffered B (one sync per tap); smem-staged coalesced fp16 epilogue.
// smem: [0, 25344)       A (3 rows x 66 px x 128B) -> xsq -> sY [oc][144B]
//       [25344, 74496)   B w-tap triple buffer (3x16KB) -> gamma in bufs 0-1
//       [74496+)         sRat(64), sBias(128), sBeta(128)
// ---------------------------------------------------------------------------
#define CV_AROW  8448
#define CV_B     25344
#define CV_RAT   74496
#define CV_BIAS  74752
#define CV_BETA  75264
#define CV_SMEM  75776

__global__ __launch_bounds__(256, 2)
void convgdn_mma_kernel(const float* __restrict__ bias,
                        const float* __restrict__ beta,
                        const float* __restrict__ mask)
{
    extern __shared__ unsigned char dsm[];
    uint32_t sbase = smem_u32(dsm);
    uint32_t sA = sbase;                  // also xsq, then sY
    uint32_t sB = sbase + CV_B;           // also gamma (bufs 0-1)
    float* sRat  = (float*)(dsm + CV_RAT);
    float* sBias = (float*)(dsm + CV_BIAS);
    float* sBeta = (float*)(dsm + CV_BETA);

    int tid = threadIdx.x;
    int lane = tid & 31, wid = tid >> 5;  // 8 warps
    int wm = (wid & 1) * 32;              // px offset (64/32)
    int wn = (wid >> 1) * 32;             // oc offset (128/32)

    int t = blockIdx.x;                   // 8192
    int b = t >> 10, rem = t & 1023;
    int h = rem >> 2, q = rem & 3;

    if (tid < 128) {
        sBias[tid] = bias[tid];
        sBeta[tid] = beta[tid];
    }

    // stage A: 3 rows x 66 px x 128B
    for (int i = tid; i < 1584; i += 256) {
        int r = i / 528, rem2 = i % 528;
        int p = rem2 >> 3, c = rem2 & 7;
        const uint4* src = g_xh4
            + ((size_t)(b*PH + h + r))*PH*8 + (size_t)(q*64 + p)*8 + c;
        cp16(sA + r*CV_AROW + p*128 + ((c ^ (p & 7)) << 4), src);
    }
    // stage B tap 0 -> buf 0
    for (int i = tid; i < 1024; i += 256) {
        int o = i >> 3, c = i & 7;
        const __half* src = g_wh + (size_t)o*64 + c*8;
        cp16(sB + o*128 + ((c ^ (o & 7)) << 4), src);
    }
    cp_commit();

    // partial-conv ratio (overlaps staging latency)
    int wq0 = q*64;
    if (tid < 64) {
        int wq = wq0 + tid;
        float s = 0.f;
        #pragma unroll
        for (int dh = -1; dh <= 1; ++dh) {
            int gh = h + dh;
            if ((unsigned)gh >= (unsigned)HH) continue;
            #pragma unroll
            for (int dw = -1; dw <= 1; ++dw) {
                int gw = wq + dw;
                if ((unsigned)gw >= (unsigned)WW) continue;
                s += mask[(b*HH + gh)*WW + gw];
            }
        }
        float ratio = s > 0.f ? 9.f / fmaxf(s, 1e-8f) : 0.f;
        sRat[tid] = ratio;
        g_ratio[(b*HH + h)*WW + wq] = ratio;
    }

    float acc[2][4][4];
    #pragma unroll
    for (int ma = 0; ma < 2; ++ma)
        #pragma unroll
        for (int nt = 0; nt < 4; ++nt)
            #pragma unroll
            for (int k = 0; k < 4; ++k) acc[ma][nt][k] = 0.f;

    for (int tap = 0; tap < 9; ++tap) {
        cp_wait0();
        __syncthreads();
        if (tap < 8) {
            int nt2 = tap + 1;
            uint32_t bu = (uint32_t)(nt2 % 3);
            for (int i = tid; i < 1024; i += 256) {
                int o = i >> 3, c = i & 7;
                const __half* src = g_wh + (size_t)(nt2*128 + o)*64 + c*8;
                cp16(sB + bu*16384 + o*128 + ((c ^ (o & 7)) << 4), src);
            }
            cp_commit();
        }
        int dh = tap / 3, dw = tap % 3;
        uint32_t abase = sA + (uint32_t)dh*CV_AROW;
        uint32_t bbase = sB + (uint32_t)(tap % 3)*16384;
        #pragma unroll
        for (int ks = 0; ks < 4; ++ks) {
            uint32_t bf[4][2];
            #pragma unroll
            for (int nb = 0; nb < 2; ++nb) {
                int n = wn + nb*16 + (lane & 7) + ((lane >> 4) << 3);
                int ch = 2*ks + ((lane >> 3) & 1);
                uint32_t r4[4];
                ldm_x4(r4, bbase + n*128 + ((ch ^ (n & 7)) << 4));
                bf[2*nb][0] = r4[0]; bf[2*nb][1] = r4[1];
                bf[2*nb+1][0] = r4[2]; bf[2*nb+1][1] = r4[3];
            }
            uint32_t a[2][4];
            #pragma unroll
            for (int ma = 0; ma < 2; ++ma) {
                int m = wm + ma*16 + (lane & 7) + ((lane >> 3) & 1)*8;
                int p = m + dw;
                int ch = 2*ks + (lane >> 4);
                ldm_x4(a[ma], abase + p*128 + ((ch ^ (p & 7)) << 4));
            }
            #pragma unroll
            for (int ma = 0; ma < 2; ++ma)
                #pragma unroll
                for (int nt = 0; nt < 4; ++nt)
                    mma_f16(acc[ma][nt], a[ma], bf[nt]);
        }
        // no trailing sync: triple buffer keeps write-after-read 2 syncs apart
    }
    __syncthreads();   // all tap reads done; A and B bufs 0-1 reusable

    // ---- load gamma into B bufs 0-1 ----
    for (int i = tid; i < 2048; i += 256) {
        int o = i >> 4, c = i & 15;
        const __half* src = g_gh + (size_t)o*128 + c*8;
        cp16(sB + o*256 + ((c ^ (o & 7)) << 4), src);
    }
    cp_commit();

    // ---- y in regs (ratio+bias), xsq=fp16(y^2) into A region [px][256B] ----
    #pragma unroll
    for (int ma = 0; ma < 2; ++ma)
        #pragma unroll
        for (int nt = 0; nt < 4; ++nt) {
            int r  = wm + ma*16 + (lane >> 2);
            int cb = wn + nt*8 + 2*(lane & 3);
            float rt0 = sRat[r], rt8 = sRat[r + 8];
            float y0 = rt0 > 0.f ? acc[ma][nt][0]*rt0 + sBias[cb]   : 0.f;
            float y1 = rt0 > 0.f ? acc[ma][nt][1]*rt0 + sBias[cb+1] : 0.f;
            float y2 = rt8 > 0.f ? acc[ma][nt][2]*rt8 + sBias[cb]   : 0.f;
            float y3 = rt8 > 0.f ? acc[ma][nt][3]*rt8 + sBias[cb+1] : 0.f;
            acc[ma][nt][0] = y0; acc[ma][nt][1] = y1;
            acc[ma][nt][2] = y2; acc[ma][nt][3] = y3;
            uint32_t c0 = (uint32_t)(cb >> 3), e0 = (uint32_t)(cb & 7);
            uint32_t c1 = (uint32_t)((cb+1) >> 3), e1 = (uint32_t)((cb+1) & 7);
            *(__half*)(dsm + (uint32_t)r*256 + ((c0 ^ (r & 7)) << 4) + e0*2)
                = __float2half_rn(y0*y0);
            *(__half*)(dsm + (uint32_t)r*256 + ((c1 ^ (r & 7)) << 4) + e1*2)
                = __float2half_rn(y1*y1);
            *(__half*)(dsm + (uint32_t)(r+8)*256 + ((c0 ^ ((r+8) & 7)) << 4) + e0*2)
                = __float2half_rn(y2*y2);
            *(__half*)(dsm + (uint32_t)(r+8)*256 + ((c1 ^ ((r+8) & 7)) << 4) + e1*2)
                = __float2half_rn(y3*y3);
        }
    cp_wait0();
    __syncthreads();

    // ---- GDN GEMM: D2[px][oc] = xsq[px][ch] @ gamma[oc][ch]^T ----
    float ac2[2][4][4];
    #pragma unroll
    for (int ma = 0; ma < 2; ++ma)
        #pragma unroll
        for (int nt = 0; nt < 4; ++nt)
            #pragma unroll
            for (int k = 0; k < 4; ++k) ac2[ma][nt][k] = 0.f;

    #pragma unroll
    for (int ks = 0; ks < 8; ++ks) {
        uint32_t a[2][4];
        #pragma unroll
        for (int ma = 0; ma < 2; ++ma) {
            int p = wm + ma*16 + (lane & 7) + ((lane >> 3) & 1)*8;
            int ch = 2*ks + (lane >> 4);
            ldm_x4(a[ma], sA + p*256 + ((ch ^ (p & 7)) << 4));
        }
        uint32_t bf[4][2];
        #pragma unroll
        for (int nb = 0; nb < 2; ++nb) {
            int n = wn + nb*16 + (lane & 7) + ((lane >> 4) << 3);
            int ch = 2*ks + ((lane >> 3) & 1);
            uint32_t r4[4];
            ldm_x4(r4, sB + n*256 + ((ch ^ (n & 7)) << 4));
            bf[2*nb][0] = r4[0]; bf[2*nb][1] = r4[1];
            bf[2*nb+1][0] = r4[2]; bf[2*nb+1][1] = r4[3];
        }
        #pragma unroll
        for (int ma = 0; ma < 2; ++ma)
            #pragma unroll
            for (int nt = 0; nt < 4; ++nt)
                mma_f16(ac2[ma][nt], a[ma], bf[nt]);
    }
    __syncthreads();   // xsq dead: A region becomes sY

    // ---- stage final fp16 y into sY [oc][px], row stride 144B ----
    #pragma unroll
    for (int ma = 0; ma < 2; ++ma)
        #pragma unroll
        for (int nt = 0; nt < 4; ++nt) {
            int r  = wm + ma*16 + (lane >> 2);
            int cb = wn + nt*8 + 2*(lane & 3);
            float be0 = sBeta[cb], be1 = sBeta[cb + 1];
            *(__half*)(dsm + (uint32_t)cb*144 + (uint32_t)r*2) =
                __float2half_rn(acc[ma][nt][0] * rsqrtf(be0 + ac2[ma][nt][0]));
            *(__half*)(dsm + (uint32_t)(cb+1)*144 + (uint32_t)r*2) =
                __float2half_rn(acc[ma][nt][1] * rsqrtf(be1 + ac2[ma][nt][1]));
            *(__half*)(dsm + (uint32_t)cb*144 + (uint32_t)(r+8)*2) =
                __float2half_rn(acc[ma][nt][2] * rsqrtf(be0 + ac2[ma][nt][2]));
            *(__half*)(dsm + (uint32_t)(cb+1)*144 + (uint32_t)(r+8)*2) =
                __float2half_rn(acc[ma][nt][3] * rsqrtf(be1 + ac2[ma][nt][3]));
        }
    __syncthreads();

    // ---- coalesced write-out: 128 oc rows x 64 px fp16 (4 x STG.128/thr) ----
    size_t gout = (size_t)b*CO*HH*WW + (size_t)h*WW + wq0;
    for (int i = tid; i < 1024; i += 256) {
        int oc = i >> 3, chk = i & 7;
        uint4 v = *(const uint4*)(dsm + (uint32_t)oc*144 + (uint32_t)chk*16);
        *(uint4*)((unsigned char*)(g_x + gout + (size_t)oc*(HH*WW)) + chk*16) = v;
    }
}

// ---------------------------------------------------------------------------
// Fused 2D DWT (CDF 9/7 analysis), fp16 input
// ---------------------------------------------------------------------------
__global__ __launch_bounds__(256)
void dwt_kernel(float* __restrict__ out)
{
    __shared__ float sT[40][72];
    __shared__ float sLo[16][72];
    __shared__ float sHi[16][72];

    int tid = threadIdx.x;
    int z = blockIdx.z;
    int hb = blockIdx.y * 16, wb = blockIdx.x * 32;
    const __half* src = g_x + (size_t)z * HH * WW;

    for (int i = tid; i < 40*72; i += 256) {
        int r = i / 72, cc = i % 72;
        int gr = refl(2*hb - 4 + r, HH);
        int gc = refl(2*wb - 4 + cc, WW);
        sT[r][cc] = __half2float(src[gr*WW + gc]);
    }
    __syncthreads();

    for (int i = tid; i < 16*72; i += 256) {
        int r = i / 72, cc = i % 72;
        float lo = 0.f, hi = 0.f;
        #pragma unroll
        for (int k = 0; k < 9; ++k) lo += c_h0[k] * sT[2*r + k][cc];
        #pragma unroll
        for (int k = 0; k < 7; ++k) hi += c_h1[k] * sT[2*r + k + 1][cc];
        sLo[r][cc] = lo;
        sHi[r][cc] = hi;
    }
    __syncthreads();

    for (int i = tid; i < 16*32; i += 256) {
        int r = i / 32, co = i % 32;
        float ll = 0.f, lh = 0.f, hl = 0.f, hh = 0.f;
        #pragma unroll
        for (int k = 0; k < 9; ++k) {
            ll += c_h0[k] * sLo[r][2*co + k];
            hl += c_h0[k] * sHi[r][2*co + k];
        }
        #pragma unroll
        for (int k = 0; k < 7; ++k) {
            lh += c_h1[k] * sLo[r][2*co + k + 1];
            hh += c_h1[k] * sHi[r][2*co + k + 1];
        }
        size_t idx = (size_t)z*16384 + (size_t)(hb + r)*128 + (wb + co);
        out[OFF_LL + idx] = ll;
        out[OFF_LH + idx] = lh;
        out[OFF_HL + idx] = hl;
        out[OFF_HH + idx] = hh;
    }
}

// ---------------------------------------------------------------------------
// Mask DWT: OR over reflected 9/7 windows
// ---------------------------------------------------------------------------
__global__ void maskdwt_kernel(float* __restrict__ out)
{
    int idx = blockIdx.x * 256 + threadIdx.x;
    if (idx >= BB*128*128) return;
    int b = idx >> 14, rem = idx & 16383;
    int ho = rem >> 7, wo = rem & 127;

    bool mll = false, mlh = false, mhl = false, mhh = false;
    #pragma unroll
    for (int dr = -4; dr <= 4; ++dr) {
        int gr = refl(2*ho + dr, HH);
        bool row9 = false, row7 = false;
        #pragma unroll
        for (int dc = -4; dc <= 4; ++dc) {
            int gc = refl(2*wo + dc, WW);
            bool v = g_ratio[(b*HH + gr)*WW + gc] > 0.f;
            row9 |= v;
            if (dc >= -3 && dc <= 3) row7 |= v;
        }
        mll |= row9;
        mlh |= row7;
        if (dr >= -3 && dr <= 3) { mhl |= row9; mhh |= row7; }
    }
    out[OFF_MLL + idx] = mll ? 1.f : 0.f;
    out[OFF_MLH + idx] = mlh ? 1.f : 0.f;
    out[OFF_MHL + idx] = mhl ? 1.f : 0.f;
    out[OFF_MHH + idx] = mhh ? 1.f : 0.f;
}

// ---------------------------------------------------------------------------
extern "C" void kernel_launch(void* const* d_in, const int* in_sizes, int n_in,
                              void* d_out, int out_size)
{
    const float* tensor = (const float*)d_in[0];
    const float* mask   = (const float*)d_in[1];
    const float* weight = (const float*)d_in[2];
    const float* bias   = (const float*)d_in[3];
    const float* u      = (const float*)d_in[4];
    const float* beta   = (const float*)d_in[5];
    const float* gamma  = (const float*)d_in[6];
    float* out = (float*)d_out;

    cudaFuncSetAttribute(convgdn_mma_kernel,
                         cudaFuncAttributeMaxDynamicSharedMemorySize, CV_SMEM);

    spectral_kernel<<<1, 256>>>(weight, u);                          // 0
    xprep_kernel<<<dim3(8, 256, 8), 256>>>(tensor, mask);            // 1
    prep_kernel<<<(9*128*64 + 128*128 + 255)/256, 256>>>(weight, gamma); // 2
    convgdn_mma_kernel<<<8192, 256, CV_SMEM>>>(bias, beta, mask);    // 3 (profiled)
    dwt_kernel<<<dim3(4, 8, BB*CO), 256>>>(out);                     // 4
    maskdwt_kernel<<<(BB*128*128 + 255)/256, 256>>>(out);            // 5
}

// round 16
// speedup vs baseline: 1.4785x; 1.1163x over previous
#include <cuda_runtime.h>
#include <cuda_fp16.h>
#include <math.h>
#include <cstdint>

#define BB 8
#define CI 64
#define CO 128
#define HH 256
#define WW 256

#define SUB (BB*CO*128*128)
#define MSK (BB*128*128)
#define OFF_LL  0
#define OFF_MLL (SUB)
#define OFF_LH  (SUB + MSK)
#define OFF_HL  (2*SUB + MSK)
#define OFF_HH  (3*SUB + MSK)
#define OFF_MLH (4*SUB + MSK)
#define OFF_MHL (4*SUB + 2*MSK)
#define OFF_MHH (4*SUB + 3*MSK)

#define PH 258

// Scratch
__device__ __half g_x[(size_t)BB*CO*HH*WW];   // GDN output (DWT input), fp16
__device__ float g_ratio[BB*HH*WW];
__device__ float g_inv_sigma;
// zero-initialized; xprep writes interior only, so borders stay zero forever
__device__ uint4 g_xh4[(size_t)BB*PH*PH*8];   // padded NHWC fp16 of x*mask
__device__ __half g_wh[9*128*64];             // [tap][oc][ch] fp16 (spectral-normalized)
__device__ __half g_gh[128*128];              // gamma [oc][ch] fp16

__constant__ float c_h0[9] = {
    0.026748757410810f, -0.016864118442875f, -0.078223266528990f,
    0.266864118442875f,  0.602949018236360f,  0.266864118442875f,
   -0.078223266528990f, -0.016864118442875f,  0.026748757410810f};
__constant__ float c_h1[7] = {
    0.091271763114250f, -0.057543526228500f, -0.591271763114250f,
    1.115087052457000f, -0.591271763114250f, -0.057543526228500f,
    0.091271763114250f};

__device__ __forceinline__ int refl(int i, int n) {
    return i < 0 ? -i : (i >= n ? 2*n - 2 - i : i);
}
__device__ __forceinline__ uint32_t smem_u32(const void* p) {
    uint32_t a;
    asm("{ .reg .u64 t; cvta.to.shared.u64 t, %1; cvt.u32.u64 %0, t; }" : "=r"(a) : "l"(p));
    return a;
}
__device__ __forceinline__ void cp16(uint32_t s, const void* g) {
    asm volatile("cp.async.cg.shared.global [%0], [%1], 16;" :: "r"(s), "l"(g));
}
__device__ __forceinline__ void cp_commit() {
    asm volatile("cp.async.commit_group;" ::: "memory");
}
__device__ __forceinline__ void cp_wait0() {
    asm volatile("cp.async.wait_group 0;" ::: "memory");
}
__device__ __forceinline__ void ldm_x4(uint32_t* r, uint32_t addr) {
    asm volatile("ldmatrix.sync.aligned.m8n8.x4.shared.b16 {%0,%1,%2,%3}, [%4];"
        : "=r"(r[0]), "=r"(r[1]), "=r"(r[2]), "=r"(r[3]) : "r"(addr));
}
__device__ __forceinline__ void mma_f16(float* c, const uint32_t* a, const uint32_t* b) {
    asm volatile(
        "mma.sync.aligned.m16n8k16.row.col.f32.f16.f16.f32 "
        "{%0,%1,%2,%3}, {%4,%5,%6,%7}, {%8,%9}, {%0,%1,%2,%3};"
        : "+f"(c[0]), "+f"(c[1]), "+f"(c[2]), "+f"(c[3])
        : "r"(a[0]), "r"(a[1]), "r"(a[2]), "r"(a[3]), "r"(b[0]), "r"(b[1]));
}
__device__ __forceinline__ uint32_t pkh(__half a, __half b) {
    return (uint32_t)__half_as_ushort(a) | ((uint32_t)__half_as_ushort(b) << 16);
}
__device__ __forceinline__ __half lo_h(uint32_t v) {
    return __ushort_as_half((unsigned short)(v & 0xFFFF));
}
__device__ __forceinline__ __half hi_h(uint32_t v) {
    return __ushort_as_half((unsigned short)(v >> 16));
}

// ---------------------------------------------------------------------------
// Spectral norm
// ---------------------------------------------------------------------------
__global__ void spectral_kernel(const float* __restrict__ w,
                                const float* __restrict__ u)
{
    __shared__ float sv[576];
    __shared__ float red[256];
    int tid = threadIdx.x;
    float p = 0.f;
    for (int j = tid; j < 576; j += 256) {
        float s = 0.f;
        #pragma unroll 4
        for (int o = 0; o < 128; ++o) s += w[o*576 + j] * u[o];
        sv[j] = s;
        p += s * s;
    }
    red[tid] = p; __syncthreads();
    for (int s = 128; s > 0; s >>= 1) {
        if (tid < s) red[tid] += red[tid + s];
        __syncthreads();
    }
    float vinv = 1.f / (sqrtf(red[0]) + 1e-12f);
    __syncthreads();
    float q = 0.f;
    if (tid < 128) {
        float s = 0.f;
        #pragma unroll 4
        for (int j = 0; j < 576; ++j) s += w[tid*576 + j] * sv[j];
        s *= vinv;
        q = s * s;
    }
    red[tid] = q; __syncthreads();
    for (int s = 128; s > 0; s >>= 1) {
        if (tid < s) red[tid] += red[tid + s];
        __syncthreads();
    }
    if (tid == 0) g_inv_sigma = rsqrtf(red[0]);
}

// ---------------------------------------------------------------------------
// xprep: coalesced reads (w across lanes) -> smem transpose -> contiguous
// uint4 writes.  CTA = (b, h, 32-w tile); 256 threads.
// ---------------------------------------------------------------------------
__global__ __launch_bounds__(256)
void xprep_kernel(const float* __restrict__ x,
                  const float* __restrict__ mask)
{
    __shared__ uint32_t sX[32*33];

    int tid = threadIdx.x;
    int lane = tid & 31, w_ = tid >> 5;
    int w0 = blockIdx.x * 32;
    int h  = blockIdx.y;
    int b  = blockIdx.z;

    float m = mask[(b*HH + h)*WW + w0 + lane];
    #pragma unroll
    for (int k = 0; k < 4; ++k) {
        int c0 = w_*8 + 2*k;
        float v0 = x[(((size_t)b*CI + c0)*HH + h)*WW + w0 + lane] * m;
        float v1 = x[(((size_t)b*CI + c0 + 1)*HH + h)*WW + w0 + lane] * m;
        sX[(w_*4 + k)*33 + lane] = pkh(__float2half_rn(v0), __float2half_rn(v1));
    }
    __syncthreads();

    int pwl = tid >> 3, j = tid & 7;
    uint4 v;
    v.x = sX[(j*4 + 0)*33 + pwl];
    v.y = sX[(j*4 + 1)*33 + pwl];
    v.z = sX[(j*4 + 2)*33 + pwl];
    v.w = sX[(j*4 + 3)*33 + pwl];
    g_xh4[((size_t)(b*PH + h + 1))*PH*8 + (size_t)(w0 + 1 + pwl)*8 + j] = v;
}

// ---------------------------------------------------------------------------
// prep: weights [tap][oc][ch] fp16 (spectral-normalized) + gamma [oc][ch] fp16
// ---------------------------------------------------------------------------
__global__ void prep_kernel(const float* __restrict__ weight,
                            const float* __restrict__ gamma)
{
    int idx = blockIdx.x * 256 + threadIdx.x;
    if (idx < 9*128*64) {
        int c = idx & 63, o = (idx >> 6) & 127, tap = idx >> 13;
        float wv = weight[(o*64 + c)*9 + tap] * g_inv_sigma;
        g_wh[(tap*128 + o)*64 + c] = __float2half_rn(wv);
    } else if (idx < 9*128*64 + 128*128) {
        int gi = idx - 9*128*64;
        g_gh[gi] = __float2half_rn(gamma[gi]);
    }
}

// ---------------------------------------------------------------------------
// Fused Conv3x3 + partial renorm + GDN.  CTA = 256 thr, 128 px x 128 oc as
// TWO sequential 64-px tiles sharing every conv B fragment (-27% crossbar).
// Warp tile 32x32; y packed fp16 in regs across GDN; 2 CTAs/SM.
// smem: [0, 49920)   A (3 rows x 130 px x 128B); post-conv: xsq [0,16K),
//                    sY [16384, 34816) stride 144
//       [49920, 99072) B w-tap triple buffer (3x16KB); post-conv gamma 32KB
//       [99072+)      sRat(128), sBias(128), sBeta(128)
// ---------------------------------------------------------------------------
#define CV_AROW  16640
#define CV_B     49920
#define CV_SY    16384
#define CV_RAT   99072
#define CV_BIAS  99584
#define CV_BETA  100096
#define CV_SMEM  100608

__global__ __launch_bounds__(256, 2)
void convgdn_mma_kernel(const float* __restrict__ bias,
                        const float* __restrict__ beta,
                        const float* __restrict__ mask)
{
    extern __shared__ unsigned char dsm[];
    uint32_t sbase = smem_u32(dsm);
    uint32_t sA = sbase;
    uint32_t sB = sbase + CV_B;
    float* sRat  = (float*)(dsm + CV_RAT);
    float* sBias = (float*)(dsm + CV_BIAS);
    float* sBeta = (float*)(dsm + CV_BETA);

    int tid = threadIdx.x;
    int lane = tid & 31, wid = tid >> 5;  // 8 warps
    int wm = (wid & 1) * 32;              // px offset within 64-px tile
    int wn = (wid >> 1) * 32;             // oc offset (128/32)

    int t = blockIdx.x;                   // 4096
    int b = t >> 9, h = (t & 511) >> 1, q = t & 1;

    if (tid < 128) {
        sBias[tid] = bias[tid];
        sBeta[tid] = beta[tid];
    }

    // stage A: 3 rows x 130 px x 128B
    for (int i = tid; i < 3120; i += 256) {
        int r = i / 1040, rem2 = i % 1040;
        int p = rem2 >> 3, c = rem2 & 7;
        const uint4* src = g_xh4
            + ((size_t)(b*PH + h + r))*PH*8 + (size_t)(q*128 + p)*8 + c;
        cp16(sA + r*CV_AROW + p*128 + ((c ^ (p & 7)) << 4), src);
    }
    // stage B tap 0 -> buf 0
    for (int i = tid; i < 1024; i += 256) {
        int o = i >> 3, c = i & 7;
        const __half* src = g_wh + (size_t)o*64 + c*8;
        cp16(sB + o*128 + ((c ^ (o & 7)) << 4), src);
    }
    cp_commit();

    // partial-conv ratio (overlaps staging latency)
    int wq0 = q*128;
    if (tid < 128) {
        int wq = wq0 + tid;
        float s = 0.f;
        #pragma unroll
        for (int dh = -1; dh <= 1; ++dh) {
            int gh = h + dh;
            if ((unsigned)gh >= (unsigned)HH) continue;
            #pragma unroll
            for (int dw = -1; dw <= 1; ++dw) {
                int gw = wq + dw;
                if ((unsigned)gw >= (unsigned)WW) continue;
                s += mask[(b*HH + gh)*WW + gw];
            }
        }
        float ratio = s > 0.f ? 9.f / fmaxf(s, 1e-8f) : 0.f;
        sRat[tid] = ratio;
        g_ratio[(b*HH + h)*WW + wq] = ratio;
    }

    float acc[2][2][4][4];
    #pragma unroll
    for (int t2 = 0; t2 < 2; ++t2)
        #pragma unroll
        for (int ma = 0; ma < 2; ++ma)
            #pragma unroll
            for (int nt = 0; nt < 4; ++nt)
                #pragma unroll
                for (int k = 0; k < 4; ++k) acc[t2][ma][nt][k] = 0.f;

    for (int tap = 0; tap < 9; ++tap) {
        cp_wait0();
        __syncthreads();
        if (tap < 8) {
            int nt2 = tap + 1;
            uint32_t bu = (uint32_t)(nt2 % 3);
            for (int i = tid; i < 1024; i += 256) {
                int o = i >> 3, c = i & 7;
                const __half* src = g_wh + (size_t)(nt2*128 + o)*64 + c*8;
                cp16(sB + bu*16384 + o*128 + ((c ^ (o & 7)) << 4), src);
            }
            cp_commit();
        }
        int dh = tap / 3, dw = tap % 3;
        uint32_t abase = sA + (uint32_t)dh*CV_AROW;
        uint32_t bbase = sB + (uint32_t)(tap % 3)*16384;
        #pragma unroll
        for (int ks = 0; ks < 4; ++ks) {
            uint32_t bf[4][2];
            #pragma unroll
            for (int nb = 0; nb < 2; ++nb) {
                int n = wn + nb*16 + (lane & 7) + ((lane >> 4) << 3);
                int ch = 2*ks + ((lane >> 3) & 1);
                uint32_t r4[4];
                ldm_x4(r4, bbase + n*128 + ((ch ^ (n & 7)) << 4));
                bf[2*nb][0] = r4[0]; bf[2*nb][1] = r4[1];
                bf[2*nb+1][0] = r4[2]; bf[2*nb+1][1] = r4[3];
            }
            #pragma unroll
            for (int t2 = 0; t2 < 2; ++t2) {
                uint32_t a[2][4];
                #pragma unroll
                for (int ma = 0; ma < 2; ++ma) {
                    int m = t2*64 + wm + ma*16 + (lane & 7) + ((lane >> 3) & 1)*8;
                    int p = m + dw;
                    int ch = 2*ks + (lane >> 4);
                    ldm_x4(a[ma], abase + p*128 + ((ch ^ (p & 7)) << 4));
                }
                #pragma unroll
                for (int ma = 0; ma < 2; ++ma)
                    #pragma unroll
                    for (int nt = 0; nt < 4; ++nt)
                        mma_f16(acc[t2][ma][nt], a[ma], bf[nt]);
            }
        }
        // triple buffer: no trailing sync
    }
    __syncthreads();   // all conv A/B reads done

    // ---- gamma into B bufs 0-1 ----
    for (int i = tid; i < 2048; i += 256) {
        int o = i >> 4, c = i & 15;
        const __half* src = g_gh + (size_t)o*128 + c*8;
        cp16(sB + o*256 + ((c ^ (o & 7)) << 4), src);
    }
    cp_commit();

    // ---- pack y (fp16) into regs, freeing acc ----
    uint32_t ypack[2][2][4][2];
    #pragma unroll
    for (int t2 = 0; t2 < 2; ++t2)
        #pragma unroll
        for (int ma = 0; ma < 2; ++ma)
            #pragma unroll
            for (int nt = 0; nt < 4; ++nt) {
                int r  = wm + ma*16 + (lane >> 2);
                int cb = wn + nt*8 + 2*(lane & 3);
                float rt0 = sRat[t2*64 + r], rt8 = sRat[t2*64 + r + 8];
                float y0 = rt0 > 0.f ? acc[t2][ma][nt][0]*rt0 + sBias[cb]   : 0.f;
                float y1 = rt0 > 0.f ? acc[t2][ma][nt][1]*rt0 + sBias[cb+1] : 0.f;
                float y2 = rt8 > 0.f ? acc[t2][ma][nt][2]*rt8 + sBias[cb]   : 0.f;
                float y3 = rt8 > 0.f ? acc[t2][ma][nt][3]*rt8 + sBias[cb+1] : 0.f;
                ypack[t2][ma][nt][0] = pkh(__float2half_rn(y0), __float2half_rn(y1));
                ypack[t2][ma][nt][1] = pkh(__float2half_rn(y2), __float2half_rn(y3));
            }

    size_t goutb = (size_t)b*CO*HH*WW + (size_t)h*WW + wq0;

    #pragma unroll
    for (int t2 = 0; t2 < 2; ++t2) {
        // ---- xsq = fp16(y^2) into A region [px][256B] (64 px tile) ----
        #pragma unroll
        for (int ma = 0; ma < 2; ++ma)
            #pragma unroll
            for (int nt = 0; nt < 4; ++nt) {
                int r  = wm + ma*16 + (lane >> 2);
                int cb = wn + nt*8 + 2*(lane & 3);
                float y0 = __half2float(lo_h(ypack[t2][ma][nt][0]));
                float y1 = __half2float(hi_h(ypack[t2][ma][nt][0]));
                float y2 = __half2float(lo_h(ypack[t2][ma][nt][1]));
                float y3 = __half2float(hi_h(ypack[t2][ma][nt][1]));
                uint32_t c0 = (uint32_t)(cb >> 3), e0 = (uint32_t)(cb & 7);
                uint32_t c1 = (uint32_t)((cb+1) >> 3), e1 = (uint32_t)((cb+1) & 7);
                *(__half*)(dsm + (uint32_t)r*256 + ((c0 ^ (r & 7)) << 4) + e0*2)
                    = __float2half_rn(y0*y0);
                *(__half*)(dsm + (uint32_t)r*256 + ((c1 ^ (r & 7)) << 4) + e1*2)
                    = __float2half_rn(y1*y1);
                *(__half*)(dsm + (uint32_t)(r+8)*256 + ((c0 ^ ((r+8) & 7)) << 4) + e0*2)
                    = __float2half_rn(y2*y2);
                *(__half*)(dsm + (uint32_t)(r+8)*256 + ((c1 ^ ((r+8) & 7)) << 4) + e1*2)
                    = __float2half_rn(y3*y3);
            }
        if (t2 == 0) cp_wait0();   // gamma ready
        __syncthreads();

        // ---- GDN GEMM: D2[px][oc] = xsq @ gamma^T ----
        float ac2[2][4][4];
        #pragma unroll
        for (int ma = 0; ma < 2; ++ma)
            #pragma unroll
            for (int nt = 0; nt < 4; ++nt)
                #pragma unroll
                for (int k = 0; k < 4; ++k) ac2[ma][nt][k] = 0.f;

        #pragma unroll
        for (int ks = 0; ks < 8; ++ks) {
            uint32_t a[2][4];
            #pragma unroll
            for (int ma = 0; ma < 2; ++ma) {
                int p = wm + ma*16 + (lane & 7) + ((lane >> 3) & 1)*8;
                int ch = 2*ks + (lane >> 4);
                ldm_x4(a[ma], sA + p*256 + ((ch ^ (p & 7)) << 4));
            }
            uint32_t bf[4][2];
            #pragma unroll
            for (int nb = 0; nb < 2; ++nb) {
                int n = wn + nb*16 + (lane & 7) + ((lane >> 4) << 3);
                int ch = 2*ks + ((lane >> 3) & 1);
                uint32_t r4[4];
                ldm_x4(r4, sB + n*256 + ((ch ^ (n & 7)) << 4));
                bf[2*nb][0] = r4[0]; bf[2*nb][1] = r4[1];
                bf[2*nb+1][0] = r4[2]; bf[2*nb+1][1] = r4[3];
            }
            #pragma unroll
            for (int ma = 0; ma < 2; ++ma)
                #pragma unroll
                for (int nt = 0; nt < 4; ++nt)
                    mma_f16(ac2[ma][nt], a[ma], bf[nt]);
        }
        __syncthreads();   // xsq reads done; sY free (prev write-out passed)

        // ---- epilogue: fp16 y * rsqrt(beta + D2) -> sY [oc][144B] ----
        #pragma unroll
        for (int ma = 0; ma < 2; ++ma)
            #pragma unroll
            for (int nt = 0; nt < 4; ++nt) {
                int r  = wm + ma*16 + (lane >> 2);
                int cb = wn + nt*8 + 2*(lane & 3);
                float be0 = sBeta[cb], be1 = sBeta[cb + 1];
                float y0 = __half2float(lo_h(ypack[t2][ma][nt][0]));
                float y1 = __half2float(hi_h(ypack[t2][ma][nt][0]));
                float y2 = __half2float(lo_h(ypack[t2][ma][nt][1]));
                float y3 = __half2float(hi_h(ypack[t2][ma][nt][1]));
                *(__half*)(dsm + CV_SY + (uint32_t)cb*144 + (uint32_t)r*2) =
                    __float2half_rn(y0 * rsqrtf(be0 + ac2[ma][nt][0]));
                *(__half*)(dsm + CV_SY + (uint32_t)(cb+1)*144 + (uint32_t)r*2) =
                    __float2half_rn(y1 * rsqrtf(be1 + ac2[ma][nt][1]));
                *(__half*)(dsm + CV_SY + (uint32_t)cb*144 + (uint32_t)(r+8)*2) =
                    __float2half_rn(y2 * rsqrtf(be0 + ac2[ma][nt][2]));
                *(__half*)(dsm + CV_SY + (uint32_t)(cb+1)*144 + (uint32_t)(r+8)*2) =
                    __float2half_rn(y3 * rsqrtf(be1 + ac2[ma][nt][3]));
            }
        __syncthreads();

        // ---- coalesced write-out: 128 oc x 64 px fp16 ----
        size_t gout = goutb + t2*64;
        for (int i = tid; i < 1024; i += 256) {
            int oc = i >> 3, chk = i & 7;
            uint4 v = *(const uint4*)(dsm + CV_SY + (uint32_t)oc*144 + (uint32_t)chk*16);
            *(uint4*)((unsigned char*)(g_x + gout + (size_t)oc*(HH*WW)) + chk*16) = v;
        }
    }
}

// ---------------------------------------------------------------------------
// Fused 2D DWT (CDF 9/7 analysis), fp16 input
// ---------------------------------------------------------------------------
__global__ __launch_bounds__(256)
void dwt_kernel(float* __restrict__ out)
{
    __shared__ float sT[40][72];
    __shared__ float sLo[16][72];
    __shared__ float sHi[16][72];

    int tid = threadIdx.x;
    int z = blockIdx.z;
    int hb = blockIdx.y * 16, wb = blockIdx.x * 32;
    const __half* src = g_x + (size_t)z * HH * WW;

    for (int i = tid; i < 40*72; i += 256) {
        int r = i / 72, cc = i % 72;
        int gr = refl(2*hb - 4 + r, HH);
        int gc = refl(2*wb - 4 + cc, WW);
        sT[r][cc] = __half2float(src[gr*WW + gc]);
    }
    __syncthreads();

    for (int i = tid; i < 16*72; i += 256) {
        int r = i / 72, cc = i % 72;
        float lo = 0.f, hi = 0.f;
        #pragma unroll
        for (int k = 0; k < 9; ++k) lo += c_h0[k] * sT[2*r + k][cc];
        #pragma unroll
        for (int k = 0; k < 7; ++k) hi += c_h1[k] * sT[2*r + k + 1][cc];
        sLo[r][cc] = lo;
        sHi[r][cc] = hi;
    }
    __syncthreads();

    for (int i = tid; i < 16*32; i += 256) {
        int r = i / 32, co = i % 32;
        float ll = 0.f, lh = 0.f, hl = 0.f, hh = 0.f;
        #pragma unroll
        for (int k = 0; k < 9; ++k) {
            ll += c_h0[k] * sLo[r][2*co + k];
            hl += c_h0[k] * sHi[r][2*co + k];
        }
        #pragma unroll
        for (int k = 0; k < 7; ++k) {
            lh += c_h1[k] * sLo[r][2*co + k + 1];
            hh += c_h1[k] * sHi[r][2*co + k + 1];
        }
        size_t idx = (size_t)z*16384 + (size_t)(hb + r)*128 + (wb + co);
        out[OFF_LL + idx] = ll;
        out[OFF_LH + idx] = lh;
        out[OFF_HL + idx] = hl;
        out[OFF_HH + idx] = hh;
    }
}

// ---------------------------------------------------------------------------
// Mask DWT: OR over reflected 9/7 windows
// ---------------------------------------------------------------------------
__global__ void maskdwt_kernel(float* __restrict__ out)
{
    int idx = blockIdx.x * 256 + threadIdx.x;
    if (idx >= BB*128*128) return;
    int b = idx >> 14, rem = idx & 16383;
    int ho = rem >> 7, wo = rem & 127;

    bool mll = false, mlh = false, mhl = false, mhh = false;
    #pragma unroll
    for (int dr = -4; dr <= 4; ++dr) {
        int gr = refl(2*ho + dr, HH);
        bool row9 = false, row7 = false;
        #pragma unroll
        for (int dc = -4; dc <= 4; ++dc) {
            int gc = refl(2*wo + dc, WW);
            bool v = g_ratio[(b*HH + gr)*WW + gc] > 0.f;
            row9 |= v;
            if (dc >= -3 && dc <= 3) row7 |= v;
        }
        mll |= row9;
        mlh |= row7;
        if (dr >= -3 && dr <= 3) { mhl |= row9; mhh |= row7; }
    }
    out[OFF_MLL + idx] = mll ? 1.f : 0.f;
    out[OFF_MLH + idx] = mlh ? 1.f : 0.f;
    out[OFF_MHL + idx] = mhl ? 1.f : 0.f;
    out[OFF_MHH + idx] = mhh ? 1.f : 0.f;
}

// ---------------------------------------------------------------------------
extern "C" void kernel_launch(void* const* d_in, const int* in_sizes, int n_in,
                              void* d_out, int out_size)
{
    const float* tensor = (const float*)d_in[0];
    const float* mask   = (const float*)d_in[1];
    const float* weight = (const float*)d_in[2];
    const float* bias   = (const float*)d_in[3];
    const float* u      = (const float*)d_in[4];
    const float* beta   = (const float*)d_in[5];
    const float* gamma  = (const float*)d_in[6];
    float* out = (float*)d_out;

    cudaFuncSetAttribute(convgdn_mma_kernel,
                         cudaFuncAttributeMaxDynamicSharedMemorySize, CV_SMEM);

    spectral_kernel<<<1, 256>>>(weight, u);                          // 0
    xprep_kernel<<<dim3(8, 256, 8), 256>>>(tensor, mask);            // 1
    prep_kernel<<<(9*128*64 + 128*128 + 255)/256, 256>>>(weight, gamma); // 2
    convgdn_mma_kernel<<<4096, 256, CV_SMEM>>>(bias, beta, mask);    // 3 (profiled)
    dwt_kernel<<<dim3(4, 8, BB*CO), 256>>>(out);                     // 4
    maskdwt_kernel<<<(BB*128*128 + 255)/256, 256>>>(out);            // 5
}

// round 17
// speedup vs baseline: 1.5374x; 1.0399x over previous
#include <cuda_runtime.h>
#include <cuda_fp16.h>
#include <math.h>
#include <cstdint>

#define BB 8
#define CI 64
#define CO 128
#define HH 256
#define WW 256

#define SUB (BB*CO*128*128)
#define MSK (BB*128*128)
#define OFF_LL  0
#define OFF_MLL (SUB)
#define OFF_LH  (SUB + MSK)
#define OFF_HL  (2*SUB + MSK)
#define OFF_HH  (3*SUB + MSK)
#define OFF_MLH (4*SUB + MSK)
#define OFF_MHL (4*SUB + 2*MSK)
#define OFF_MHH (4*SUB + 3*MSK)

#define PH 258

// Scratch
__device__ __half g_x[(size_t)BB*CO*HH*WW];   // GDN output (DWT input), fp16
__device__ float g_ratio[BB*HH*WW];
__device__ float g_inv_sigma;
// zero-initialized; xprep writes interior only, so borders stay zero forever
__device__ uint4 g_xh4[(size_t)BB*PH*PH*8];   // padded NHWC fp16 of x*mask
__device__ __half g_wh[9*128*64];             // [tap][oc][ch] fp16 (spectral-normalized)
__device__ __half g_gh[128*128];              // gamma [oc][ch] fp16

__constant__ float c_h0[9] = {
    0.026748757410810f, -0.016864118442875f, -0.078223266528990f,
    0.266864118442875f,  0.602949018236360f,  0.266864118442875f,
   -0.078223266528990f, -0.016864118442875f,  0.026748757410810f};
__constant__ float c_h1[7] = {
    0.091271763114250f, -0.057543526228500f, -0.591271763114250f,
    1.115087052457000f, -0.591271763114250f, -0.057543526228500f,
    0.091271763114250f};

__device__ __forceinline__ int refl(int i, int n) {
    return i < 0 ? -i : (i >= n ? 2*n - 2 - i : i);
}
__device__ __forceinline__ uint32_t smem_u32(const void* p) {
    uint32_t a;
    asm("{ .reg .u64 t; cvta.to.shared.u64 t, %1; cvt.u32.u64 %0, t; }" : "=r"(a) : "l"(p));
    return a;
}
__device__ __forceinline__ void cp16(uint32_t s, const void* g) {
    asm volatile("cp.async.cg.shared.global [%0], [%1], 16;" :: "r"(s), "l"(g));
}
__device__ __forceinline__ void cp_commit() {
    asm volatile("cp.async.commit_group;" ::: "memory");
}
__device__ __forceinline__ void cp_wait0() {
    asm volatile("cp.async.wait_group 0;" ::: "memory");
}
__device__ __forceinline__ void ldm_x4(uint32_t* r, uint32_t addr) {
    asm volatile("ldmatrix.sync.aligned.m8n8.x4.shared.b16 {%0,%1,%2,%3}, [%4];"
        : "=r"(r[0]), "=r"(r[1]), "=r"(r[2]), "=r"(r[3]) : "r"(addr));
}
__device__ __forceinline__ void mma_f16(float* c, const uint32_t* a, const uint32_t* b) {
    asm volatile(
        "mma.sync.aligned.m16n8k16.row.col.f32.f16.f16.f32 "
        "{%0,%1,%2,%3}, {%4,%5,%6,%7}, {%8,%9}, {%0,%1,%2,%3};"
        : "+f"(c[0]), "+f"(c[1]), "+f"(c[2]), "+f"(c[3])
        : "r"(a[0]), "r"(a[1]), "r"(a[2]), "r"(a[3]), "r"(b[0]), "r"(b[1]));
}
__device__ __forceinline__ uint32_t pkh(__half a, __half b) {
    return (uint32_t)__half_as_ushort(a) | ((uint32_t)__half_as_ushort(b) << 16);
}
__device__ __forceinline__ __half lo_h(uint32_t v) {
    return __ushort_as_half((unsigned short)(v & 0xFFFF));
}
__device__ __forceinline__ __half hi_h(uint32_t v) {
    return __ushort_as_half((unsigned short)(v >> 16));
}

// ---------------------------------------------------------------------------
// Spectral norm
// ---------------------------------------------------------------------------
__global__ void spectral_kernel(const float* __restrict__ w,
                                const float* __restrict__ u)
{
    __shared__ float sv[576];
    __shared__ float red[256];
    int tid = threadIdx.x;
    float p = 0.f;
    for (int j = tid; j < 576; j += 256) {
        float s = 0.f;
        #pragma unroll 4
        for (int o = 0; o < 128; ++o) s += w[o*576 + j] * u[o];
        sv[j] = s;
        p += s * s;
    }
    red[tid] = p; __syncthreads();
    for (int s = 128; s > 0; s >>= 1) {
        if (tid < s) red[tid] += red[tid + s];
        __syncthreads();
    }
    float vinv = 1.f / (sqrtf(red[0]) + 1e-12f);
    __syncthreads();
    float q = 0.f;
    if (tid < 128) {
        float s = 0.f;
        #pragma unroll 4
        for (int j = 0; j < 576; ++j) s += w[tid*576 + j] * sv[j];
        s *= vinv;
        q = s * s;
    }
    red[tid] = q; __syncthreads();
    for (int s = 128; s > 0; s >>= 1) {
        if (tid < s) red[tid] += red[tid + s];
        __syncthreads();
    }
    if (tid == 0) g_inv_sigma = rsqrtf(red[0]);
}

// ---------------------------------------------------------------------------
// xprep: coalesced reads (w across lanes) -> smem transpose -> contiguous
// uint4 writes.  CTA = (b, h, 32-w tile); 256 threads.
// ---------------------------------------------------------------------------
__global__ __launch_bounds__(256)
void xprep_kernel(const float* __restrict__ x,
                  const float* __restrict__ mask)
{
    __shared__ uint32_t sX[32*33];

    int tid = threadIdx.x;
    int lane = tid & 31, w_ = tid >> 5;
    int w0 = blockIdx.x * 32;
    int h  = blockIdx.y;
    int b  = blockIdx.z;

    float m = mask[(b*HH + h)*WW + w0 + lane];
    #pragma unroll
    for (int k = 0; k < 4; ++k) {
        int c0 = w_*8 + 2*k;
        float v0 = x[(((size_t)b*CI + c0)*HH + h)*WW + w0 + lane] * m;
        float v1 = x[(((size_t)b*CI + c0 + 1)*HH + h)*WW + w0 + lane] * m;
        sX[(w_*4 + k)*33 + lane] = pkh(__float2half_rn(v0), __float2half_rn(v1));
    }
    __syncthreads();

    int pwl = tid >> 3, j = tid & 7;
    uint4 v;
    v.x = sX[(j*4 + 0)*33 + pwl];
    v.y = sX[(j*4 + 1)*33 + pwl];
    v.z = sX[(j*4 + 2)*33 + pwl];
    v.w = sX[(j*4 + 3)*33 + pwl];
    g_xh4[((size_t)(b*PH + h + 1))*PH*8 + (size_t)(w0 + 1 + pwl)*8 + j] = v;
}

// ---------------------------------------------------------------------------
// prep: weights [tap][oc][ch] fp16 (spectral-normalized) + gamma [oc][ch] fp16
// ---------------------------------------------------------------------------
__global__ void prep_kernel(const float* __restrict__ weight,
                            const float* __restrict__ gamma)
{
    int idx = blockIdx.x * 256 + threadIdx.x;
    if (idx < 9*128*64) {
        int c = idx & 63, o = (idx >> 6) & 127, tap = idx >> 13;
        float wv = weight[(o*64 + c)*9 + tap] * g_inv_sigma;
        g_wh[(tap*128 + o)*64 + c] = __float2half_rn(wv);
    } else if (idx < 9*128*64 + 128*128) {
        int gi = idx - 9*128*64;
        g_gh[gi] = __float2half_rn(gamma[gi]);
    }
}

// ---------------------------------------------------------------------------
// Fused Conv3x3 + partial renorm + GDN.  CTA = 256 thr, 128 px x 128 oc as
// TWO sequential 64-px tiles sharing every conv B fragment.  (R16 winner)
// ---------------------------------------------------------------------------
#define CV_AROW  16640
#define CV_B     49920
#define CV_SY    16384
#define CV_RAT   99072
#define CV_BIAS  99584
#define CV_BETA  100096
#define CV_SMEM  100608

__global__ __launch_bounds__(256, 2)
void convgdn_mma_kernel(const float* __restrict__ bias,
                        const float* __restrict__ beta,
                        const float* __restrict__ mask)
{
    extern __shared__ unsigned char dsm[];
    uint32_t sbase = smem_u32(dsm);
    uint32_t sA = sbase;
    uint32_t sB = sbase + CV_B;
    float* sRat  = (float*)(dsm + CV_RAT);
    float* sBias = (float*)(dsm + CV_BIAS);
    float* sBeta = (float*)(dsm + CV_BETA);

    int tid = threadIdx.x;
    int lane = tid & 31, wid = tid >> 5;
    int wm = (wid & 1) * 32;
    int wn = (wid >> 1) * 32;

    int t = blockIdx.x;
    int b = t >> 9, h = (t & 511) >> 1, q = t & 1;

    if (tid < 128) {
        sBias[tid] = bias[tid];
        sBeta[tid] = beta[tid];
    }

    for (int i = tid; i < 3120; i += 256) {
        int r = i / 1040, rem2 = i % 1040;
        int p = rem2 >> 3, c = rem2 & 7;
        const uint4* src = g_xh4
            + ((size_t)(b*PH + h + r))*PH*8 + (size_t)(q*128 + p)*8 + c;
        cp16(sA + r*CV_AROW + p*128 + ((c ^ (p & 7)) << 4), src);
    }
    for (int i = tid; i < 1024; i += 256) {
        int o = i >> 3, c = i & 7;
        const __half* src = g_wh + (size_t)o*64 + c*8;
        cp16(sB + o*128 + ((c ^ (o & 7)) << 4), src);
    }
    cp_commit();

    int wq0 = q*128;
    if (tid < 128) {
        int wq = wq0 + tid;
        float s = 0.f;
        #pragma unroll
        for (int dh = -1; dh <= 1; ++dh) {
            int gh = h + dh;
            if ((unsigned)gh >= (unsigned)HH) continue;
            #pragma unroll
            for (int dw = -1; dw <= 1; ++dw) {
                int gw = wq + dw;
                if ((unsigned)gw >= (unsigned)WW) continue;
                s += mask[(b*HH + gh)*WW + gw];
            }
        }
        float ratio = s > 0.f ? 9.f / fmaxf(s, 1e-8f) : 0.f;
        sRat[tid] = ratio;
        g_ratio[(b*HH + h)*WW + wq] = ratio;
    }

    float acc[2][2][4][4];
    #pragma unroll
    for (int t2 = 0; t2 < 2; ++t2)
        #pragma unroll
        for (int ma = 0; ma < 2; ++ma)
            #pragma unroll
            for (int nt = 0; nt < 4; ++nt)
                #pragma unroll
                for (int k = 0; k < 4; ++k) acc[t2][ma][nt][k] = 0.f;

    for (int tap = 0; tap < 9; ++tap) {
        cp_wait0();
        __syncthreads();
        if (tap < 8) {
            int nt2 = tap + 1;
            uint32_t bu = (uint32_t)(nt2 % 3);
            for (int i = tid; i < 1024; i += 256) {
                int o = i >> 3, c = i & 7;
                const __half* src = g_wh + (size_t)(nt2*128 + o)*64 + c*8;
                cp16(sB + bu*16384 + o*128 + ((c ^ (o & 7)) << 4), src);
            }
            cp_commit();
        }
        int dh = tap / 3, dw = tap % 3;
        uint32_t abase = sA + (uint32_t)dh*CV_AROW;
        uint32_t bbase = sB + (uint32_t)(tap % 3)*16384;
        #pragma unroll
        for (int ks = 0; ks < 4; ++ks) {
            uint32_t bf[4][2];
            #pragma unroll
            for (int nb = 0; nb < 2; ++nb) {
                int n = wn + nb*16 + (lane & 7) + ((lane >> 4) << 3);
                int ch = 2*ks + ((lane >> 3) & 1);
                uint32_t r4[4];
                ldm_x4(r4, bbase + n*128 + ((ch ^ (n & 7)) << 4));
                bf[2*nb][0] = r4[0]; bf[2*nb][1] = r4[1];
                bf[2*nb+1][0] = r4[2]; bf[2*nb+1][1] = r4[3];
            }
            #pragma unroll
            for (int t2 = 0; t2 < 2; ++t2) {
                uint32_t a[2][4];
                #pragma unroll
                for (int ma = 0; ma < 2; ++ma) {
                    int m = t2*64 + wm + ma*16 + (lane & 7) + ((lane >> 3) & 1)*8;
                    int p = m + dw;
                    int ch = 2*ks + (lane >> 4);
                    ldm_x4(a[ma], abase + p*128 + ((ch ^ (p & 7)) << 4));
                }
                #pragma unroll
                for (int ma = 0; ma < 2; ++ma)
                    #pragma unroll
                    for (int nt = 0; nt < 4; ++nt)
                        mma_f16(acc[t2][ma][nt], a[ma], bf[nt]);
            }
        }
    }
    __syncthreads();

    for (int i = tid; i < 2048; i += 256) {
        int o = i >> 4, c = i & 15;
        const __half* src = g_gh + (size_t)o*128 + c*8;
        cp16(sB + o*256 + ((c ^ (o & 7)) << 4), src);
    }
    cp_commit();

    uint32_t ypack[2][2][4][2];
    #pragma unroll
    for (int t2 = 0; t2 < 2; ++t2)
        #pragma unroll
        for (int ma = 0; ma < 2; ++ma)
            #pragma unroll
            for (int nt = 0; nt < 4; ++nt) {
                int r  = wm + ma*16 + (lane >> 2);
                int cb = wn + nt*8 + 2*(lane & 3);
                float rt0 = sRat[t2*64 + r], rt8 = sRat[t2*64 + r + 8];
                float y0 = rt0 > 0.f ? acc[t2][ma][nt][0]*rt0 + sBias[cb]   : 0.f;
                float y1 = rt0 > 0.f ? acc[t2][ma][nt][1]*rt0 + sBias[cb+1] : 0.f;
                float y2 = rt8 > 0.f ? acc[t2][ma][nt][2]*rt8 + sBias[cb]   : 0.f;
                float y3 = rt8 > 0.f ? acc[t2][ma][nt][3]*rt8 + sBias[cb+1] : 0.f;
                ypack[t2][ma][nt][0] = pkh(__float2half_rn(y0), __float2half_rn(y1));
                ypack[t2][ma][nt][1] = pkh(__float2half_rn(y2), __float2half_rn(y3));
            }

    size_t goutb = (size_t)b*CO*HH*WW + (size_t)h*WW + wq0;

    #pragma unroll
    for (int t2 = 0; t2 < 2; ++t2) {
        #pragma unroll
        for (int ma = 0; ma < 2; ++ma)
            #pragma unroll
            for (int nt = 0; nt < 4; ++nt) {
                int r  = wm + ma*16 + (lane >> 2);
                int cb = wn + nt*8 + 2*(lane & 3);
                float y0 = __half2float(lo_h(ypack[t2][ma][nt][0]));
                float y1 = __half2float(hi_h(ypack[t2][ma][nt][0]));
                float y2 = __half2float(lo_h(ypack[t2][ma][nt][1]));
                float y3 = __half2float(hi_h(ypack[t2][ma][nt][1]));
                uint32_t c0 = (uint32_t)(cb >> 3), e0 = (uint32_t)(cb & 7);
                uint32_t c1 = (uint32_t)((cb+1) >> 3), e1 = (uint32_t)((cb+1) & 7);
                *(__half*)(dsm + (uint32_t)r*256 + ((c0 ^ (r & 7)) << 4) + e0*2)
                    = __float2half_rn(y0*y0);
                *(__half*)(dsm + (uint32_t)r*256 + ((c1 ^ (r & 7)) << 4) + e1*2)
                    = __float2half_rn(y1*y1);
                *(__half*)(dsm + (uint32_t)(r+8)*256 + ((c0 ^ ((r+8) & 7)) << 4) + e0*2)
                    = __float2half_rn(y2*y2);
                *(__half*)(dsm + (uint32_t)(r+8)*256 + ((c1 ^ ((r+8) & 7)) << 4) + e1*2)
                    = __float2half_rn(y3*y3);
            }
        if (t2 == 0) cp_wait0();
        __syncthreads();

        float ac2[2][4][4];
        #pragma unroll
        for (int ma = 0; ma < 2; ++ma)
            #pragma unroll
            for (int nt = 0; nt < 4; ++nt)
                #pragma unroll
                for (int k = 0; k < 4; ++k) ac2[ma][nt][k] = 0.f;

        #pragma unroll
        for (int ks = 0; ks < 8; ++ks) {
            uint32_t a[2][4];
            #pragma unroll
            for (int ma = 0; ma < 2; ++ma) {
                int p = wm + ma*16 + (lane & 7) + ((lane >> 3) & 1)*8;
                int ch = 2*ks + (lane >> 4);
                ldm_x4(a[ma], sA + p*256 + ((ch ^ (p & 7)) << 4));
            }
            uint32_t bf[4][2];
            #pragma unroll
            for (int nb = 0; nb < 2; ++nb) {
                int n = wn + nb*16 + (lane & 7) + ((lane >> 4) << 3);
                int ch = 2*ks + ((lane >> 3) & 1);
                uint32_t r4[4];
                ldm_x4(r4, sB + n*256 + ((ch ^ (n & 7)) << 4));
                bf[2*nb][0] = r4[0]; bf[2*nb][1] = r4[1];
                bf[2*nb+1][0] = r4[2]; bf[2*nb+1][1] = r4[3];
            }
            #pragma unroll
            for (int ma = 0; ma < 2; ++ma)
                #pragma unroll
                for (int nt = 0; nt < 4; ++nt)
                    mma_f16(ac2[ma][nt], a[ma], bf[nt]);
        }
        __syncthreads();

        #pragma unroll
        for (int ma = 0; ma < 2; ++ma)
            #pragma unroll
            for (int nt = 0; nt < 4; ++nt) {
                int r  = wm + ma*16 + (lane >> 2);
                int cb = wn + nt*8 + 2*(lane & 3);
                float be0 = sBeta[cb], be1 = sBeta[cb + 1];
                float y0 = __half2float(lo_h(ypack[t2][ma][nt][0]));
                float y1 = __half2float(hi_h(ypack[t2][ma][nt][0]));
                float y2 = __half2float(lo_h(ypack[t2][ma][nt][1]));
                float y3 = __half2float(hi_h(ypack[t2][ma][nt][1]));
                *(__half*)(dsm + CV_SY + (uint32_t)cb*144 + (uint32_t)r*2) =
                    __float2half_rn(y0 * rsqrtf(be0 + ac2[ma][nt][0]));
                *(__half*)(dsm + CV_SY + (uint32_t)(cb+1)*144 + (uint32_t)r*2) =
                    __float2half_rn(y1 * rsqrtf(be1 + ac2[ma][nt][1]));
                *(__half*)(dsm + CV_SY + (uint32_t)cb*144 + (uint32_t)(r+8)*2) =
                    __float2half_rn(y2 * rsqrtf(be0 + ac2[ma][nt][2]));
                *(__half*)(dsm + CV_SY + (uint32_t)(cb+1)*144 + (uint32_t)(r+8)*2) =
                    __float2half_rn(y3 * rsqrtf(be1 + ac2[ma][nt][3]));
            }
        __syncthreads();

        size_t gout = goutb + t2*64;
        for (int i = tid; i < 1024; i += 256) {
            int oc = i >> 3, chk = i & 7;
            uint4 v = *(const uint4*)(dsm + CV_SY + (uint32_t)oc*144 + (uint32_t)chk*16);
            *(uint4*)((unsigned char*)(g_x + gout + (size_t)oc*(HH*WW)) + chk*16) = v;
        }
    }
}

// ---------------------------------------------------------------------------
// Fused 2D DWT (CDF 9/7 analysis), fp16 input, 32x32 output tiles (halo 1.27x)
// ---------------------------------------------------------------------------
__global__ __launch_bounds__(256)
void dwt_kernel(float* __restrict__ out)
{
    __shared__ float sT[72][76];
    __shared__ float sLo[32][76];
    __shared__ float sHi[32][76];

    int tid = threadIdx.x;
    int z = blockIdx.z;
    int hb = blockIdx.y * 32, wb = blockIdx.x * 32;   // OUTPUT coords
    const __half* src = g_x + (size_t)z * HH * WW;

    for (int i = tid; i < 72*72; i += 256) {
        int r = i / 72, cc = i % 72;
        int gr = refl(2*hb - 4 + r, HH);
        int gc = refl(2*wb - 4 + cc, WW);
        sT[r][cc] = __half2float(src[gr*WW + gc]);
    }
    __syncthreads();

    for (int i = tid; i < 32*72; i += 256) {
        int r = i / 72, cc = i % 72;
        float lo = 0.f, hi = 0.f;
        #pragma unroll
        for (int k = 0; k < 9; ++k) lo += c_h0[k] * sT[2*r + k][cc];
        #pragma unroll
        for (int k = 0; k < 7; ++k) hi += c_h1[k] * sT[2*r + k + 1][cc];
        sLo[r][cc] = lo;
        sHi[r][cc] = hi;
    }
    __syncthreads();

    for (int i = tid; i < 32*32; i += 256) {
        int r = i / 32, co = i % 32;
        float ll = 0.f, lh = 0.f, hl = 0.f, hh = 0.f;
        #pragma unroll
        for (int k = 0; k < 9; ++k) {
            ll += c_h0[k] * sLo[r][2*co + k];
            hl += c_h0[k] * sHi[r][2*co + k];
        }
        #pragma unroll
        for (int k = 0; k < 7; ++k) {
            lh += c_h1[k] * sLo[r][2*co + k + 1];
            hh += c_h1[k] * sHi[r][2*co + k + 1];
        }
        size_t idx = (size_t)z*16384 + (size_t)(hb + r)*128 + (wb + co);
        out[OFF_LL + idx] = ll;
        out[OFF_LH + idx] = lh;
        out[OFF_HL + idx] = hl;
        out[OFF_HH + idx] = hh;
    }
}

// ---------------------------------------------------------------------------
// Mask DWT: OR over reflected 9/7 windows, smem row cache.
// Block = (b, 2 output rows, 128 wo); loads 11 g_ratio rows into smem.
// ---------------------------------------------------------------------------
__global__ __launch_bounds__(256)
void maskdwt_kernel(float* __restrict__ out)
{
    __shared__ float sV[11][256];

    int tid = threadIdx.x;
    int blk = blockIdx.x;             // 512 blocks
    int b = blk >> 6;                 // 64 blocks per batch
    int ho0 = (blk & 63) * 2;         // output row pair

    // load 11 input rows (2*ho0-4 .. 2*ho0+6), row-reflected
    for (int i = tid; i < 11*256; i += 256) {
        int j = i >> 8, w = i & 255;
        int gr = refl(2*ho0 - 4 + j, HH);
        sV[j][w] = g_ratio[(b*HH + gr)*WW + w];
    }
    __syncthreads();

    // 256 threads = 2 rows x 128 wo
    int dro = tid >> 7;               // 0 or 1
    int wo  = tid & 127;
    int ho  = ho0 + dro;

    bool mll = false, mlh = false, mhl = false, mhh = false;
    #pragma unroll
    for (int dr = -4; dr <= 4; ++dr) {
        int j = 2*dro + dr + 4;       // 0..10
        bool row9 = false, row7 = false;
        #pragma unroll
        for (int dc = -4; dc <= 4; ++dc) {
            int gc = refl(2*wo + dc, WW);
            bool v = sV[j][gc] > 0.f;
            row9 |= v;
            if (dc >= -3 && dc <= 3) row7 |= v;
        }
        mll |= row9;
        mlh |= row7;
        if (dr >= -3 && dr <= 3) { mhl |= row9; mhh |= row7; }
    }
    int idx = (b << 14) + (ho << 7) + wo;
    out[OFF_MLL + idx] = mll ? 1.f : 0.f;
    out[OFF_MLH + idx] = mlh ? 1.f : 0.f;
    out[OFF_MHL + idx] = mhl ? 1.f : 0.f;
    out[OFF_MHH + idx] = mhh ? 1.f : 0.f;
}

// ---------------------------------------------------------------------------
extern "C" void kernel_launch(void* const* d_in, const int* in_sizes, int n_in,
                              void* d_out, int out_size)
{
    const float* tensor = (const float*)d_in[0];
    const float* mask   = (const float*)d_in[1];
    const float* weight = (const float*)d_in[2];
    const float* bias   = (const float*)d_in[3];
    const float* u      = (const float*)d_in[4];
    const float* beta   = (const float*)d_in[5];
    const float* gamma  = (const float*)d_in[6];
    float* out = (float*)d_out;

    cudaFuncSetAttribute(convgdn_mma_kernel,
                         cudaFuncAttributeMaxDynamicSharedMemorySize, CV_SMEM);

    spectral_kernel<<<1, 256>>>(weight, u);                          // 0
    xprep_kernel<<<dim3(8, 256, 8), 256>>>(tensor, mask);            // 1
    prep_kernel<<<(9*128*64 + 128*128 + 255)/256, 256>>>(weight, gamma); // 2
    convgdn_mma_kernel<<<4096, 256, CV_SMEM>>>(bias, beta, mask);    // 3 (profiled)
    dwt_kernel<<<dim3(4, 4, BB*CO), 256>>>(out);                     // 4
    maskdwt_kernel<<<512, 256>>>(out);                               // 5
}